// round 13
// baseline (speedup 1.0000x reference)
#include <cuda_runtime.h>
#include <cuda_fp16.h>
#include <math.h>

#define NN    100000
#define DIM   128
#define HEADS 8
#define NE    1600000
#define NEG   0.2f
#define LNEPS 1e-5f
#define HID   512
#define GB_ROWS 782            // ceil(NN/128)
#define SCAN_NB 98             // ceil(NN/1024)

#define OFF_WG 0
#define OFF_W1 16384           // 128*128
#define OFF_W2 81920           // + 128*512
#define WTOT   147456          // + 512*128

// ---------------- scratch (static device globals; no allocation) -------------
__device__ __half g_h16 [(size_t)NN * DIM];   // x@Wg (fp16)
__device__ __half g_z   [(size_t)NN * HID];   // FFN hidden (fp16)
__device__ float  g_asrc[NN * HEADS];
__device__ float  g_adst[NN * HEADS];
__device__ __half g_wT  [WTOT];               // W^T fp16 [n][k]
__device__ int    g_counts  [NN];
__device__ int    g_cursors [NN];
__device__ int    g_offsets [NN + 1];
__device__ int    g_csr     [NE];
__device__ int    g_blocksum[SCAN_NB];
__device__ int    g_blockoff[SCAN_NB];
__device__ int    g_is64;

// ---------------- prep: zero counters + edge dtype detection ------------------
__global__ void k_prep(const unsigned int* __restrict__ ew) {
    int i = blockIdx.x * blockDim.x + threadIdx.x;
    if (i < NN) { g_counts[i] = 0; g_cursors[i] = 0; }
    if (i == 0) {
        unsigned int acc = 0;
        #pragma unroll
        for (int t = 0; t < 16; ++t) acc |= ew[2 * t + 1];
        g_is64 = (acc == 0) ? 1 : 0;
    }
}

__device__ __forceinline__ int edge_at(const void* ei, int is64, size_t idx) {
    if (is64) return (int)((const long long*)ei)[idx];
    return ((const int*)ei)[idx];
}

__global__ void k_hist(const void* __restrict__ ei) {
    int i = blockIdx.x * blockDim.x + threadIdx.x;
    if (i >= NE) return;
    int dst = edge_at(ei, g_is64, (size_t)NE + i);
    if ((unsigned)dst < (unsigned)NN) atomicAdd(&g_counts[dst], 1);
}

__global__ __launch_bounds__(1024) void k_scan_part() {
    __shared__ int ws[32];
    int tid = threadIdx.x;
    int i = blockIdx.x * 1024 + tid;
    int v = (i < NN) ? g_counts[i] : 0;
    int lane = tid & 31, wid = tid >> 5;
    int x = v;
    #pragma unroll
    for (int o = 1; o < 32; o <<= 1) {
        int y = __shfl_up_sync(0xFFFFFFFFu, x, o);
        if (lane >= o) x += y;
    }
    if (lane == 31) ws[wid] = x;
    __syncthreads();
    if (wid == 0) {
        int s = ws[lane];
        #pragma unroll
        for (int o = 1; o < 32; o <<= 1) {
            int y = __shfl_up_sync(0xFFFFFFFFu, s, o);
            if (lane >= o) s += y;
        }
        ws[lane] = s;
    }
    __syncthreads();
    int base = wid ? ws[wid - 1] : 0;
    int incl = base + x;
    if (i < NN) g_offsets[i] = incl - v;
    if (tid == 1023) g_blocksum[blockIdx.x] = incl;
}

__global__ void k_scan_tops() {
    __shared__ int ws[4];
    int t = threadIdx.x;
    int v = (t < SCAN_NB) ? g_blocksum[t] : 0;
    int lane = t & 31, wid = t >> 5;
    int x = v;
    #pragma unroll
    for (int o = 1; o < 32; o <<= 1) {
        int y = __shfl_up_sync(0xFFFFFFFFu, x, o);
        if (lane >= o) x += y;
    }
    if (lane == 31) ws[wid] = x;
    __syncthreads();
    int add = 0;
    for (int w = 0; w < wid; ++w) add += ws[w];
    x += add;
    if (t < SCAN_NB) g_blockoff[t] = x - v;
    if (t == SCAN_NB - 1) g_offsets[NN] = x;
}

__global__ __launch_bounds__(1024) void k_scan_add() {
    int i = blockIdx.x * 1024 + threadIdx.x;
    if (i < NN) g_offsets[i] += g_blockoff[blockIdx.x];
}

__global__ void k_scatter(const void* __restrict__ ei) {
    int i = blockIdx.x * blockDim.x + threadIdx.x;
    if (i >= NE) return;
    int src = edge_at(ei, g_is64, i);
    int dst = edge_at(ei, g_is64, (size_t)NE + i);
    if ((unsigned)src < (unsigned)NN && (unsigned)dst < (unsigned)NN) {
        int pos = g_offsets[dst] + atomicAdd(&g_cursors[dst], 1);
        g_csr[pos] = src;
    }
}

// -------- all-weights convert+transpose (fp32 [k][n] -> fp16 [n][k]) ----------
__global__ void k_convT_all(const float* __restrict__ Wg,
                            const float* __restrict__ W1,
                            const float* __restrict__ W2) {
    int i = blockIdx.x * blockDim.x + threadIdx.x;
    if (i >= WTOT) return;
    const float* src; int K, N, off, loc;
    if (i < OFF_W1)      { src = Wg; K = DIM; N = DIM; off = OFF_WG; loc = i; }
    else if (i < OFF_W2) { src = W1; K = DIM; N = HID; off = OFF_W1; loc = i - OFF_W1; }
    else                 { src = W2; K = HID; N = DIM; off = OFF_W2; loc = i - OFF_W2; }
    int k = loc / N, n = loc % N;
    g_wT[off + n * K + k] = __float2half_rn(src[loc]);
}

// ---------------- mma / cp.async helpers --------------------------------------
__device__ __forceinline__ void mma_f16(float* c, const unsigned* a,
                                        unsigned b0, unsigned b1) {
    asm volatile(
        "mma.sync.aligned.m16n8k16.row.col.f32.f16.f16.f32 "
        "{%0,%1,%2,%3}, {%4,%5,%6,%7}, {%8,%9}, {%0,%1,%2,%3};"
        : "+f"(c[0]), "+f"(c[1]), "+f"(c[2]), "+f"(c[3])
        : "r"(a[0]), "r"(a[1]), "r"(a[2]), "r"(a[3]), "r"(b0), "r"(b1));
}
__device__ __forceinline__ unsigned smem_u32(const void* p) {
    return (unsigned)__cvta_generic_to_shared(p);
}
__device__ __forceinline__ void cp16(unsigned dst, const void* src) {
    asm volatile("cp.async.cg.shared.global [%0], [%1], 16;"
                 :: "r"(dst), "l"(src));
}
__device__ __forceinline__ void cp_commit() {
    asm volatile("cp.async.commit_group;");
}
__device__ __forceinline__ void cp_wait0() {
    asm volatile("cp.async.wait_group 0;");
}
__device__ __forceinline__ float gelu_exact(float t) {
    return 0.5f * t * (1.0f + erff(t * 0.70710678118654752f));
}

// -------- GEMM1: g_h16 = x @ Wg (fp16), attn coefficients in epilogue --------
__global__ __launch_bounds__(256) void k_gemm1(
    const float* __restrict__ x,
    const float* __restrict__ att_s, const float* __restrict__ att_d)
{
    __shared__ __half sA[2][128][40];
    __shared__ __half sB[2][128][40];

    const int tid  = threadIdx.x;
    const int lane = tid & 31;
    const int wid  = tid >> 5;
    const int warpM = wid & 3;
    const int warpN = wid >> 2;
    const int rowBase = blockIdx.x * 128;

    auto load_chunk = [&](int c, int st) {
        int k0 = c * 32;
        #pragma unroll
        for (int t = 0; t < 4; ++t) {
            int s = tid + t * 256;
            int m = s >> 3, kq = s & 7;
            int gr = rowBase + m;
            float4 v = (gr < NN) ? *(const float4*)&x[(size_t)gr * DIM + k0 + kq * 4]
                                 : make_float4(0.f, 0.f, 0.f, 0.f);
            *(__half2*)&sA[st][m][kq * 4]     = __floats2half2_rn(v.x, v.y);
            *(__half2*)&sA[st][m][kq * 4 + 2] = __floats2half2_rn(v.z, v.w);
        }
        #pragma unroll
        for (int t = 0; t < 2; ++t) {
            int s = tid + t * 256;
            int n = s >> 2, ko = (s & 3) * 8;
            cp16(smem_u32(&sB[st][n][ko]),
                 &g_wT[OFF_WG + (size_t)n * DIM + k0 + ko]);
        }
        cp_commit();
    };

    float acc[2][8][4];
    #pragma unroll
    for (int mi = 0; mi < 2; ++mi)
        #pragma unroll
        for (int ni = 0; ni < 8; ++ni)
            #pragma unroll
            for (int q = 0; q < 4; ++q) acc[mi][ni][q] = 0.f;

    load_chunk(0, 0);
    for (int c = 0; c < 4; ++c) {
        cp_wait0();
        __syncthreads();
        if (c + 1 < 4) load_chunk(c + 1, (c + 1) & 1);
        const int st = c & 1;
        #pragma unroll
        for (int ks = 0; ks < 2; ++ks) {
            unsigned ah[2][4];
            #pragma unroll
            for (int mi = 0; mi < 2; ++mi) {
                int r0 = warpM * 32 + mi * 16 + (lane >> 2);
                int r1 = r0 + 8;
                int c0 = ks * 16 + (lane & 3) * 2;
                ah[mi][0] = *(const unsigned*)&sA[st][r0][c0];
                ah[mi][1] = *(const unsigned*)&sA[st][r1][c0];
                ah[mi][2] = *(const unsigned*)&sA[st][r0][c0 + 8];
                ah[mi][3] = *(const unsigned*)&sA[st][r1][c0 + 8];
            }
            #pragma unroll
            for (int ni = 0; ni < 8; ++ni) {
                int nr = warpN * 64 + ni * 8 + (lane >> 2);
                int c0 = ks * 16 + (lane & 3) * 2;
                unsigned b0 = *(const unsigned*)&sB[st][nr][c0];
                unsigned b1 = *(const unsigned*)&sB[st][nr][c0 + 8];
                mma_f16(acc[0][ni], ah[0], b0, b1);
                mma_f16(acc[1][ni], ah[1], b0, b1);
            }
        }
        __syncthreads();
    }

    // epilogue: store h16 + attention partial dots (head group = warpN*4 + ni/2)
    float ps[2][2][4], pd[2][2][4];
    #pragma unroll
    for (int mi = 0; mi < 2; ++mi)
        #pragma unroll
        for (int rh = 0; rh < 2; ++rh)
            #pragma unroll
            for (int hg = 0; hg < 4; ++hg) { ps[mi][rh][hg] = 0.f; pd[mi][rh][hg] = 0.f; }

    #pragma unroll
    for (int ni = 0; ni < 8; ++ni) {
        int cc = warpN * 64 + ni * 8 + (lane & 3) * 2;
        float2 as = *(const float2*)&att_s[cc];
        float2 ad = *(const float2*)&att_d[cc];
        int hg = ni >> 1;
        #pragma unroll
        for (int mi = 0; mi < 2; ++mi) {
            int r0 = rowBase + warpM * 32 + mi * 16 + (lane >> 2);
            int r1 = r0 + 8;
            float x0 = acc[mi][ni][0], x1 = acc[mi][ni][1];
            float x2 = acc[mi][ni][2], x3 = acc[mi][ni][3];
            ps[mi][0][hg] += x0 * as.x + x1 * as.y;
            ps[mi][1][hg] += x2 * as.x + x3 * as.y;
            pd[mi][0][hg] += x0 * ad.x + x1 * ad.y;
            pd[mi][1][hg] += x2 * ad.x + x3 * ad.y;
            if (r0 < NN) *(__half2*)&g_h16[(size_t)r0 * DIM + cc] = __floats2half2_rn(x0, x1);
            if (r1 < NN) *(__half2*)&g_h16[(size_t)r1 * DIM + cc] = __floats2half2_rn(x2, x3);
        }
    }
    #pragma unroll
    for (int o = 1; o < 4; o <<= 1)
        #pragma unroll
        for (int mi = 0; mi < 2; ++mi)
            #pragma unroll
            for (int rh = 0; rh < 2; ++rh)
                #pragma unroll
                for (int hg = 0; hg < 4; ++hg) {
                    ps[mi][rh][hg] += __shfl_xor_sync(0xFFFFFFFFu, ps[mi][rh][hg], o);
                    pd[mi][rh][hg] += __shfl_xor_sync(0xFFFFFFFFu, pd[mi][rh][hg], o);
                }
    if ((lane & 3) == 0) {
        #pragma unroll
        for (int mi = 0; mi < 2; ++mi)
            #pragma unroll
            for (int rh = 0; rh < 2; ++rh) {
                int r = rowBase + warpM * 32 + mi * 16 + (lane >> 2) + rh * 8;
                if (r < NN) {
                    #pragma unroll
                    for (int hg = 0; hg < 4; ++hg) {
                        g_asrc[r * 8 + warpN * 4 + hg] = ps[mi][rh][hg];
                        g_adst[r * 8 + warpN * 4 + hg] = pd[mi][rh][hg];
                    }
                }
            }
    }
}

// -------- FFN1: z = gelu(h1@W1+b1)  (col-tiled, R10 config) -------------------
__global__ __launch_bounds__(256) void k_ffn1t(
    const float* __restrict__ h1, const float* __restrict__ b1)
{
    __shared__ __half sA[2][128][40];
    __shared__ __half sB[2][128][40];

    const int tid  = threadIdx.x;
    const int lane = tid & 31;
    const int wid  = tid >> 5;
    const int warpM = wid & 3;
    const int warpN = wid >> 2;
    const int rowBase = blockIdx.x * 128;
    const int colBase = blockIdx.y * 128;

    auto load_chunk = [&](int c, int st) {
        int k0 = c * 32;
        #pragma unroll
        for (int t = 0; t < 4; ++t) {
            int s = tid + t * 256;
            int m = s >> 3, kq = s & 7;
            int gr = rowBase + m;
            float4 v = (gr < NN) ? *(const float4*)&h1[(size_t)gr * DIM + k0 + kq * 4]
                                 : make_float4(0.f, 0.f, 0.f, 0.f);
            *(__half2*)&sA[st][m][kq * 4]     = __floats2half2_rn(v.x, v.y);
            *(__half2*)&sA[st][m][kq * 4 + 2] = __floats2half2_rn(v.z, v.w);
        }
        #pragma unroll
        for (int t = 0; t < 2; ++t) {
            int s = tid + t * 256;
            int n = s >> 2, ko = (s & 3) * 8;
            cp16(smem_u32(&sB[st][n][ko]),
                 &g_wT[OFF_W1 + (size_t)(colBase + n) * DIM + k0 + ko]);
        }
        cp_commit();
    };

    float acc[2][8][4];
    #pragma unroll
    for (int mi = 0; mi < 2; ++mi)
        #pragma unroll
        for (int ni = 0; ni < 8; ++ni)
            #pragma unroll
            for (int q = 0; q < 4; ++q) acc[mi][ni][q] = 0.f;

    load_chunk(0, 0);
    for (int c = 0; c < 4; ++c) {
        cp_wait0();
        __syncthreads();
        if (c + 1 < 4) load_chunk(c + 1, (c + 1) & 1);
        const int st = c & 1;
        #pragma unroll
        for (int ks = 0; ks < 2; ++ks) {
            unsigned ah[2][4];
            #pragma unroll
            for (int mi = 0; mi < 2; ++mi) {
                int r0 = warpM * 32 + mi * 16 + (lane >> 2);
                int r1 = r0 + 8;
                int c0 = ks * 16 + (lane & 3) * 2;
                ah[mi][0] = *(const unsigned*)&sA[st][r0][c0];
                ah[mi][1] = *(const unsigned*)&sA[st][r1][c0];
                ah[mi][2] = *(const unsigned*)&sA[st][r0][c0 + 8];
                ah[mi][3] = *(const unsigned*)&sA[st][r1][c0 + 8];
            }
            #pragma unroll
            for (int ni = 0; ni < 8; ++ni) {
                int nr = warpN * 64 + ni * 8 + (lane >> 2);
                int c0 = ks * 16 + (lane & 3) * 2;
                unsigned b0 = *(const unsigned*)&sB[st][nr][c0];
                unsigned b1w = *(const unsigned*)&sB[st][nr][c0 + 8];
                mma_f16(acc[0][ni], ah[0], b0, b1w);
                mma_f16(acc[1][ni], ah[1], b0, b1w);
            }
        }
        __syncthreads();
    }

    #pragma unroll
    for (int mi = 0; mi < 2; ++mi) {
        int r0 = rowBase + warpM * 32 + mi * 16 + (lane >> 2);
        int r1 = r0 + 8;
        #pragma unroll
        for (int ni = 0; ni < 8; ++ni) {
            int c = colBase + warpN * 64 + ni * 8 + (lane & 3) * 2;
            float bb0 = b1[c], bb1 = b1[c + 1];
            float x0 = gelu_exact(acc[mi][ni][0] + bb0);
            float x1 = gelu_exact(acc[mi][ni][1] + bb1);
            float x2 = gelu_exact(acc[mi][ni][2] + bb0);
            float x3 = gelu_exact(acc[mi][ni][3] + bb1);
            if (r0 < NN) *(__half2*)&g_z[(size_t)r0 * HID + c] = __floats2half2_rn(x0, x1);
            if (r1 < NN) *(__half2*)&g_z[(size_t)r1 * HID + c] = __floats2half2_rn(x2, x3);
        }
    }
}

// -------- FFN2 + residual + LN2: io = LN(io + z@W2 + b2) ---------------------
__global__ __launch_bounds__(256) void k_ffn2t(
    const float* __restrict__ b2,
    const float* __restrict__ gamma, const float* __restrict__ beta,
    float* __restrict__ io)
{
    __shared__ __half sA[2][128][40];
    __shared__ __half sB[2][128][40];
    __shared__ float  redS[2][128];
    __shared__ float  redQ[2][128];

    const int tid  = threadIdx.x;
    const int lane = tid & 31;
    const int wid  = tid >> 5;
    const int warpM = wid & 3;
    const int warpN = wid >> 2;
    const int rowBase = blockIdx.x * 128;

    auto load_chunk = [&](int c, int st) {
        int k0 = c * 32;
        #pragma unroll
        for (int t = 0; t < 2; ++t) {
            int s = tid + t * 256;
            int m = s >> 2, ko = (s & 3) * 8;
            int gr = rowBase + m;
            const __half* gp = &g_z[(size_t)(gr < NN ? gr : 0) * HID + k0 + ko];
            cp16(smem_u32(&sA[st][m][ko]), gp);
        }
        #pragma unroll
        for (int t = 0; t < 2; ++t) {
            int s = tid + t * 256;
            int n = s >> 2, ko = (s & 3) * 8;
            cp16(smem_u32(&sB[st][n][ko]),
                 &g_wT[OFF_W2 + (size_t)n * HID + k0 + ko]);
        }
        cp_commit();
    };

    float acc[2][8][4];
    #pragma unroll
    for (int mi = 0; mi < 2; ++mi)
        #pragma unroll
        for (int ni = 0; ni < 8; ++ni)
            #pragma unroll
            for (int q = 0; q < 4; ++q) acc[mi][ni][q] = 0.f;

    load_chunk(0, 0);
    for (int c = 0; c < 16; ++c) {
        cp_wait0();
        __syncthreads();
        if (c + 1 < 16) load_chunk(c + 1, (c + 1) & 1);
        const int st = c & 1;
        #pragma unroll
        for (int ks = 0; ks < 2; ++ks) {
            unsigned ah[2][4];
            #pragma unroll
            for (int mi = 0; mi < 2; ++mi) {
                int r0 = warpM * 32 + mi * 16 + (lane >> 2);
                int r1 = r0 + 8;
                int c0 = ks * 16 + (lane & 3) * 2;
                ah[mi][0] = *(const unsigned*)&sA[st][r0][c0];
                ah[mi][1] = *(const unsigned*)&sA[st][r1][c0];
                ah[mi][2] = *(const unsigned*)&sA[st][r0][c0 + 8];
                ah[mi][3] = *(const unsigned*)&sA[st][r1][c0 + 8];
            }
            #pragma unroll
            for (int ni = 0; ni < 8; ++ni) {
                int nr = warpN * 64 + ni * 8 + (lane >> 2);
                int c0 = ks * 16 + (lane & 3) * 2;
                unsigned b0 = *(const unsigned*)&sB[st][nr][c0];
                unsigned b1w = *(const unsigned*)&sB[st][nr][c0 + 8];
                mma_f16(acc[0][ni], ah[0], b0, b1w);
                mma_f16(acc[1][ni], ah[1], b0, b1w);
            }
        }
        __syncthreads();
    }

    float sS[2][2] = {{0.f, 0.f}, {0.f, 0.f}};
    float sQ[2][2] = {{0.f, 0.f}, {0.f, 0.f}};
    #pragma unroll
    for (int mi = 0; mi < 2; ++mi) {
        int r0 = rowBase + warpM * 32 + mi * 16 + (lane >> 2);
        int r1 = r0 + 8;
        #pragma unroll
        for (int ni = 0; ni < 8; ++ni) {
            int c = warpN * 64 + ni * 8 + (lane & 3) * 2;
            float bb0 = b2[c], bb1 = b2[c + 1];
            float2 i0 = (r0 < NN) ? *(const float2*)&io[(size_t)r0 * DIM + c]
                                  : make_float2(0.f, 0.f);
            float2 i1 = (r1 < NN) ? *(const float2*)&io[(size_t)r1 * DIM + c]
                                  : make_float2(0.f, 0.f);
            float v0 = acc[mi][ni][0] + bb0 + i0.x;
            float v1 = acc[mi][ni][1] + bb1 + i0.y;
            float v2 = acc[mi][ni][2] + bb0 + i1.x;
            float v3 = acc[mi][ni][3] + bb1 + i1.y;
            acc[mi][ni][0] = v0; acc[mi][ni][1] = v1;
            acc[mi][ni][2] = v2; acc[mi][ni][3] = v3;
            sS[mi][0] += v0 + v1;       sS[mi][1] += v2 + v3;
            sQ[mi][0] += v0*v0 + v1*v1; sQ[mi][1] += v2*v2 + v3*v3;
        }
    }
    #pragma unroll
    for (int mi = 0; mi < 2; ++mi)
        #pragma unroll
        for (int k = 0; k < 2; ++k)
            #pragma unroll
            for (int o = 1; o < 4; o <<= 1) {
                sS[mi][k] += __shfl_xor_sync(0xFFFFFFFFu, sS[mi][k], o);
                sQ[mi][k] += __shfl_xor_sync(0xFFFFFFFFu, sQ[mi][k], o);
            }
    if ((lane & 3) == 0) {
        #pragma unroll
        for (int mi = 0; mi < 2; ++mi) {
            int lr = warpM * 32 + mi * 16 + (lane >> 2);
            redS[warpN][lr]     = sS[mi][0];
            redS[warpN][lr + 8] = sS[mi][1];
            redQ[warpN][lr]     = sQ[mi][0];
            redQ[warpN][lr + 8] = sQ[mi][1];
        }
    }
    __syncthreads();
    #pragma unroll
    for (int mi = 0; mi < 2; ++mi) {
        int lr0 = warpM * 32 + mi * 16 + (lane >> 2);
        int lr1 = lr0 + 8;
        float S0 = redS[0][lr0] + redS[1][lr0];
        float S1 = redS[0][lr1] + redS[1][lr1];
        float Q0 = redQ[0][lr0] + redQ[1][lr0];
        float Q1 = redQ[0][lr1] + redQ[1][lr1];
        float mu0 = S0 * (1.f / DIM), mu1 = S1 * (1.f / DIM);
        float rs0 = rsqrtf(fmaxf(Q0 * (1.f / DIM) - mu0 * mu0, 0.f) + LNEPS);
        float rs1 = rsqrtf(fmaxf(Q1 * (1.f / DIM) - mu1 * mu1, 0.f) + LNEPS);
        int r0 = rowBase + lr0;
        int r1 = rowBase + lr1;
        #pragma unroll
        for (int ni = 0; ni < 8; ++ni) {
            int c = warpN * 64 + ni * 8 + (lane & 3) * 2;
            float2 gv = *(const float2*)&gamma[c];
            float2 bv = *(const float2*)&beta[c];
            if (r0 < NN) {
                float2 o0;
                o0.x = gv.x * (acc[mi][ni][0] - mu0) * rs0 + bv.x;
                o0.y = gv.y * (acc[mi][ni][1] - mu0) * rs0 + bv.y;
                *(float2*)&io[(size_t)r0 * DIM + c] = o0;
            }
            if (r1 < NN) {
                float2 o1;
                o1.x = gv.x * (acc[mi][ni][2] - mu1) * rs1 + bv.x;
                o1.y = gv.y * (acc[mi][ni][3] - mu1) * rs1 + bv.y;
                *(float2*)&io[(size_t)r1 * DIM + c] = o1;
            }
        }
    }
}

// -------- aggregation + residual + LN1, cooperative exp (1 warp / node) ------
// Edge chunk of 4: lane L computes exp for (edge L>>3, head L&7) -> 1 exp/lane.
// p for (edge e, head h) lives on lane e*8+h; accumulation lane (head myh=lane>>2,
// dims 4*lane..) fetches p via shfl from lane e*8+myh.
__device__ __forceinline__ float leaky(float v) { return fmaxf(v, NEG * v); }

__global__ __launch_bounds__(256) void k_agg_ln(
    const float* __restrict__ x, const float* __restrict__ bg,
    const float* __restrict__ gamma, const float* __restrict__ beta,
    float* __restrict__ h1)
{
    int w = (blockIdx.x * blockDim.x + threadIdx.x) >> 5;
    if (w >= NN) return;
    const int lane = threadIdx.x & 31;
    const int myh = lane >> 2;       // head for accumulation (dims 4*lane..)
    const int hL  = lane & 7;        // head for cooperative exp

    const float adm   = g_adst[w * 8 + myh];
    const float asm_  = g_asrc[w * 8 + myh];
    const float ad_hL = g_adst[w * 8 + hL];

    const int beg = g_offsets[w];
    const int end = g_offsets[w + 1];

    float l = 0.f;
    float a0 = 0.f, a1 = 0.f, a2 = 0.f, a3 = 0.f;
    {   // self loop
        float p = __expf(leaky(asm_ + adm));
        l += p;
        uint2 u = *(const uint2*)&g_h16[(size_t)w * DIM + lane * 4];
        float2 h0 = __half22float2(*(__half2*)&u.x);
        float2 h1v = __half22float2(*(__half2*)&u.y);
        a0 += p * h0.x; a1 += p * h0.y; a2 += p * h1v.x; a3 += p * h1v.y;
    }

    int j = beg;
    for (; j + 3 < end; j += 4) {
        // lane's own edge for exp: e = lane>>3
        int sMine = g_csr[j + (lane >> 3)];
        float pMine = __expf(leaky(g_asrc[sMine * 8 + hL] + ad_hL));

        // gather p for head myh of each of the 4 edges + src indices
        float p0 = __shfl_sync(0xFFFFFFFFu, pMine, 0 * 8 + myh);
        float p1 = __shfl_sync(0xFFFFFFFFu, pMine, 1 * 8 + myh);
        float p2 = __shfl_sync(0xFFFFFFFFu, pMine, 2 * 8 + myh);
        float p3 = __shfl_sync(0xFFFFFFFFu, pMine, 3 * 8 + myh);
        int s0 = __shfl_sync(0xFFFFFFFFu, sMine, 0);
        int s1 = __shfl_sync(0xFFFFFFFFu, sMine, 8);
        int s2 = __shfl_sync(0xFFFFFFFFu, sMine, 16);
        int s3 = __shfl_sync(0xFFFFFFFFu, sMine, 24);

        uint2 u0 = *(const uint2*)&g_h16[(size_t)s0 * DIM + lane * 4];
        uint2 u1 = *(const uint2*)&g_h16[(size_t)s1 * DIM + lane * 4];
        uint2 u2 = *(const uint2*)&g_h16[(size_t)s2 * DIM + lane * 4];
        uint2 u3 = *(const uint2*)&g_h16[(size_t)s3 * DIM + lane * 4];
        l += p0 + p1 + p2 + p3;
        float2 q0 = __half22float2(*(__half2*)&u0.x);
        float2 q1 = __half22float2(*(__half2*)&u0.y);
        float2 r0 = __half22float2(*(__half2*)&u1.x);
        float2 r1 = __half22float2(*(__half2*)&u1.y);
        float2 t0 = __half22float2(*(__half2*)&u2.x);
        float2 t1 = __half22float2(*(__half2*)&u2.y);
        float2 v0 = __half22float2(*(__half2*)&u3.x);
        float2 v1 = __half22float2(*(__half2*)&u3.y);
        a0 += p0 * q0.x + p1 * r0.x + p2 * t0.x + p3 * v0.x;
        a1 += p0 * q0.y + p1 * r0.y + p2 * t0.y + p3 * v0.y;
        a2 += p0 * q1.x + p1 * r1.x + p2 * t1.x + p3 * v1.x;
        a3 += p0 * q1.y + p1 * r1.y + p2 * t1.y + p3 * v1.y;
    }
    for (; j < end; ++j) {
        int s = g_csr[j];
        float p = __expf(leaky(g_asrc[s * 8 + myh] + adm));
        l += p;
        uint2 u = *(const uint2*)&g_h16[(size_t)s * DIM + lane * 4];
        float2 h0 = __half22float2(*(__half2*)&u.x);
        float2 h1v = __half22float2(*(__half2*)&u.y);
        a0 += p * h0.x; a1 += p * h0.y; a2 += p * h1v.x; a3 += p * h1v.y;
    }
    float inv = 1.f / (l + 1e-16f);

    float4 xv  = *(const float4*)&x[(size_t)w * DIM + lane * 4];
    float4 bgv = *(const float4*)&bg[lane * 4];
    float4 v;
    v.x = xv.x + a0 * inv + bgv.x;
    v.y = xv.y + a1 * inv + bgv.y;
    v.z = xv.z + a2 * inv + bgv.z;
    v.w = xv.w + a3 * inv + bgv.w;

    float s = v.x + v.y + v.z + v.w;
    #pragma unroll
    for (int o = 16; o > 0; o >>= 1) s += __shfl_xor_sync(0xFFFFFFFFu, s, o);
    float mu = s * (1.f / DIM);
    v.x -= mu; v.y -= mu; v.z -= mu; v.w -= mu;
    float q = v.x * v.x + v.y * v.y + v.z * v.z + v.w * v.w;
    #pragma unroll
    for (int o = 16; o > 0; o >>= 1) q += __shfl_xor_sync(0xFFFFFFFFu, q, o);
    float rs = rsqrtf(q * (1.f / DIM) + LNEPS);
    float4 g  = *(const float4*)&gamma[lane * 4];
    float4 be = *(const float4*)&beta[lane * 4];
    float4 o4;
    o4.x = g.x * v.x * rs + be.x;
    o4.y = g.y * v.y * rs + be.y;
    o4.z = g.z * v.z * rs + be.z;
    o4.w = g.w * v.w * rs + be.w;
    *(float4*)&h1[(size_t)w * DIM + lane * 4] = o4;
}

// ---------------- launcher: forked capture branches ---------------------------
extern "C" void kernel_launch(void* const* d_in, const int* in_sizes, int n_in,
                              void* d_out, int out_size)
{
    const float* x     = (const float*)d_in[0];
    const void*  ei    = d_in[1];
    const float* Wg    = (const float*)d_in[2];
    const float* att_s = (const float*)d_in[3];
    const float* att_d = (const float*)d_in[4];
    const float* bg    = (const float*)d_in[5];
    const float* gamma = (const float*)d_in[6];
    const float* beta  = (const float*)d_in[7];
    const float* W1    = (const float*)d_in[8];
    const float* b1    = (const float*)d_in[9];
    const float* W2    = (const float*)d_in[10];
    const float* b2    = (const float*)d_in[11];
    float*       out   = (float*)d_out;

    cudaStream_t sB;
    cudaStreamCreateWithFlags(&sB, cudaStreamNonBlocking);
    cudaEvent_t evFork, evJoin;
    cudaEventCreateWithFlags(&evFork, cudaEventDisableTiming);
    cudaEventCreateWithFlags(&evJoin, cudaEventDisableTiming);

    cudaEventRecord(evFork, 0);
    cudaStreamWaitEvent(sB, evFork, 0);

    // Branch A (main stream): edge/CSR pipeline
    k_prep<<<(NN + 255) / 256, 256>>>((const unsigned int*)ei);
    k_hist<<<(NE + 255) / 256, 256>>>(ei);
    k_scan_part<<<SCAN_NB, 1024>>>();
    k_scan_tops<<<1, 128>>>();
    k_scan_add<<<SCAN_NB, 1024>>>();
    k_scatter<<<(NE + 255) / 256, 256>>>(ei);

    // Branch B (side stream): weights + gemm1 (+attn fused)
    k_convT_all<<<(WTOT + 255) / 256, 256, 0, sB>>>(Wg, W1, W2);
    k_gemm1<<<GB_ROWS, 256, 0, sB>>>(x, att_s, att_d);

    cudaEventRecord(evJoin, sB);
    cudaStreamWaitEvent(0, evJoin, 0);

    // Joined tail
    k_agg_ln<<<(NN * 32 + 255) / 256, 256>>>(x, bg, gamma, beta, out);
    k_ffn1t<<<dim3(GB_ROWS, HID / 128), 256>>>(out, b1);
    k_ffn2t<<<GB_ROWS, 256>>>(b2, gamma, beta, out);
}

// round 14
// speedup vs baseline: 1.0165x; 1.0165x over previous
#include <cuda_runtime.h>
#include <cuda_fp16.h>
#include <math.h>

#define NN    100000
#define DIM   128
#define HEADS 8
#define NE    1600000
#define NEG   0.2f
#define LNEPS 1e-5f
#define HID   512
#define GB_ROWS 782            // ceil(NN/128)
#define SCAN_NB 98             // ceil(NN/1024)

#define OFF_WG 0
#define OFF_W1 16384           // 128*128
#define OFF_W2 81920           // + 128*512
#define WTOT   147456          // + 512*128

// ---------------- scratch (static device globals; no allocation) -------------
__device__ __half g_h16 [(size_t)NN * DIM];   // x@Wg (fp16)
__device__ __half g_z   [(size_t)NN * HID];   // FFN hidden (fp16)
__device__ float2 g_easrc[NN * HEADS];        // (exp(a_src), exp(0.2 a_src))
__device__ float2 g_eadst[NN * HEADS];        // (exp(a_dst), exp(0.2 a_dst))
__device__ __half g_wT  [WTOT];               // W^T fp16 [n][k]
__device__ int    g_counts  [NN];
__device__ int    g_cursors [NN];
__device__ int    g_offsets [NN + 1];
__device__ int    g_csr     [NE];
__device__ int    g_blocksum[SCAN_NB];
__device__ int    g_blockoff[SCAN_NB];
__device__ int    g_is64;

// ---------------- prep: zero counters + edge dtype detection ------------------
__global__ void k_prep(const unsigned int* __restrict__ ew) {
    int i = blockIdx.x * blockDim.x + threadIdx.x;
    if (i < NN) { g_counts[i] = 0; g_cursors[i] = 0; }
    if (i == 0) {
        unsigned int acc = 0;
        #pragma unroll
        for (int t = 0; t < 16; ++t) acc |= ew[2 * t + 1];
        g_is64 = (acc == 0) ? 1 : 0;
    }
}

__device__ __forceinline__ int edge_at(const void* ei, int is64, size_t idx) {
    if (is64) return (int)((const long long*)ei)[idx];
    return ((const int*)ei)[idx];
}

__global__ void k_hist(const void* __restrict__ ei) {
    int i = blockIdx.x * blockDim.x + threadIdx.x;
    if (i >= NE) return;
    int dst = edge_at(ei, g_is64, (size_t)NE + i);
    if ((unsigned)dst < (unsigned)NN) atomicAdd(&g_counts[dst], 1);
}

__global__ __launch_bounds__(1024) void k_scan_part() {
    __shared__ int ws[32];
    int tid = threadIdx.x;
    int i = blockIdx.x * 1024 + tid;
    int v = (i < NN) ? g_counts[i] : 0;
    int lane = tid & 31, wid = tid >> 5;
    int x = v;
    #pragma unroll
    for (int o = 1; o < 32; o <<= 1) {
        int y = __shfl_up_sync(0xFFFFFFFFu, x, o);
        if (lane >= o) x += y;
    }
    if (lane == 31) ws[wid] = x;
    __syncthreads();
    if (wid == 0) {
        int s = ws[lane];
        #pragma unroll
        for (int o = 1; o < 32; o <<= 1) {
            int y = __shfl_up_sync(0xFFFFFFFFu, s, o);
            if (lane >= o) s += y;
        }
        ws[lane] = s;
    }
    __syncthreads();
    int base = wid ? ws[wid - 1] : 0;
    int incl = base + x;
    if (i < NN) g_offsets[i] = incl - v;
    if (tid == 1023) g_blocksum[blockIdx.x] = incl;
}

__global__ void k_scan_tops() {
    __shared__ int ws[4];
    int t = threadIdx.x;
    int v = (t < SCAN_NB) ? g_blocksum[t] : 0;
    int lane = t & 31, wid = t >> 5;
    int x = v;
    #pragma unroll
    for (int o = 1; o < 32; o <<= 1) {
        int y = __shfl_up_sync(0xFFFFFFFFu, x, o);
        if (lane >= o) x += y;
    }
    if (lane == 31) ws[wid] = x;
    __syncthreads();
    int add = 0;
    for (int w = 0; w < wid; ++w) add += ws[w];
    x += add;
    if (t < SCAN_NB) g_blockoff[t] = x - v;
    if (t == SCAN_NB - 1) g_offsets[NN] = x;
}

__global__ __launch_bounds__(1024) void k_scan_add() {
    int i = blockIdx.x * 1024 + threadIdx.x;
    if (i < NN) g_offsets[i] += g_blockoff[blockIdx.x];
}

__global__ void k_scatter(const void* __restrict__ ei) {
    int i = blockIdx.x * blockDim.x + threadIdx.x;
    if (i >= NE) return;
    int src = edge_at(ei, g_is64, i);
    int dst = edge_at(ei, g_is64, (size_t)NE + i);
    if ((unsigned)src < (unsigned)NN && (unsigned)dst < (unsigned)NN) {
        int pos = g_offsets[dst] + atomicAdd(&g_cursors[dst], 1);
        g_csr[pos] = src;
    }
}

// -------- all-weights convert+transpose (fp32 [k][n] -> fp16 [n][k]) ----------
__global__ void k_convT_all(const float* __restrict__ Wg,
                            const float* __restrict__ W1,
                            const float* __restrict__ W2) {
    int i = blockIdx.x * blockDim.x + threadIdx.x;
    if (i >= WTOT) return;
    const float* src; int K, N, off, loc;
    if (i < OFF_W1)      { src = Wg; K = DIM; N = DIM; off = OFF_WG; loc = i; }
    else if (i < OFF_W2) { src = W1; K = DIM; N = HID; off = OFF_W1; loc = i - OFF_W1; }
    else                 { src = W2; K = HID; N = DIM; off = OFF_W2; loc = i - OFF_W2; }
    int k = loc / N, n = loc % N;
    g_wT[off + n * K + k] = __float2half_rn(src[loc]);
}

// ---------------- mma / cp.async helpers --------------------------------------
__device__ __forceinline__ void mma_f16(float* c, const unsigned* a,
                                        unsigned b0, unsigned b1) {
    asm volatile(
        "mma.sync.aligned.m16n8k16.row.col.f32.f16.f16.f32 "
        "{%0,%1,%2,%3}, {%4,%5,%6,%7}, {%8,%9}, {%0,%1,%2,%3};"
        : "+f"(c[0]), "+f"(c[1]), "+f"(c[2]), "+f"(c[3])
        : "r"(a[0]), "r"(a[1]), "r"(a[2]), "r"(a[3]), "r"(b0), "r"(b1));
}
__device__ __forceinline__ unsigned smem_u32(const void* p) {
    return (unsigned)__cvta_generic_to_shared(p);
}
__device__ __forceinline__ void cp16(unsigned dst, const void* src) {
    asm volatile("cp.async.cg.shared.global [%0], [%1], 16;"
                 :: "r"(dst), "l"(src));
}
__device__ __forceinline__ void cp_commit() {
    asm volatile("cp.async.commit_group;");
}
__device__ __forceinline__ void cp_wait0() {
    asm volatile("cp.async.wait_group 0;");
}
__device__ __forceinline__ float gelu_exact(float t) {
    return 0.5f * t * (1.0f + erff(t * 0.70710678118654752f));
}

// -------- GEMM1: g_h16 = x @ Wg, epilogue: attn coeffs -> exp forms ----------
__global__ __launch_bounds__(256) void k_gemm1(
    const float* __restrict__ x,
    const float* __restrict__ att_s, const float* __restrict__ att_d)
{
    __shared__ __half sA[2][128][40];
    __shared__ __half sB[2][128][40];

    const int tid  = threadIdx.x;
    const int lane = tid & 31;
    const int wid  = tid >> 5;
    const int warpM = wid & 3;
    const int warpN = wid >> 2;
    const int rowBase = blockIdx.x * 128;

    auto load_chunk = [&](int c, int st) {
        int k0 = c * 32;
        #pragma unroll
        for (int t = 0; t < 4; ++t) {
            int s = tid + t * 256;
            int m = s >> 3, kq = s & 7;
            int gr = rowBase + m;
            float4 v = (gr < NN) ? *(const float4*)&x[(size_t)gr * DIM + k0 + kq * 4]
                                 : make_float4(0.f, 0.f, 0.f, 0.f);
            *(__half2*)&sA[st][m][kq * 4]     = __floats2half2_rn(v.x, v.y);
            *(__half2*)&sA[st][m][kq * 4 + 2] = __floats2half2_rn(v.z, v.w);
        }
        #pragma unroll
        for (int t = 0; t < 2; ++t) {
            int s = tid + t * 256;
            int n = s >> 2, ko = (s & 3) * 8;
            cp16(smem_u32(&sB[st][n][ko]),
                 &g_wT[OFF_WG + (size_t)n * DIM + k0 + ko]);
        }
        cp_commit();
    };

    float acc[2][8][4];
    #pragma unroll
    for (int mi = 0; mi < 2; ++mi)
        #pragma unroll
        for (int ni = 0; ni < 8; ++ni)
            #pragma unroll
            for (int q = 0; q < 4; ++q) acc[mi][ni][q] = 0.f;

    load_chunk(0, 0);
    for (int c = 0; c < 4; ++c) {
        cp_wait0();
        __syncthreads();
        if (c + 1 < 4) load_chunk(c + 1, (c + 1) & 1);
        const int st = c & 1;
        #pragma unroll
        for (int ks = 0; ks < 2; ++ks) {
            unsigned ah[2][4];
            #pragma unroll
            for (int mi = 0; mi < 2; ++mi) {
                int r0 = warpM * 32 + mi * 16 + (lane >> 2);
                int r1 = r0 + 8;
                int c0 = ks * 16 + (lane & 3) * 2;
                ah[mi][0] = *(const unsigned*)&sA[st][r0][c0];
                ah[mi][1] = *(const unsigned*)&sA[st][r1][c0];
                ah[mi][2] = *(const unsigned*)&sA[st][r0][c0 + 8];
                ah[mi][3] = *(const unsigned*)&sA[st][r1][c0 + 8];
            }
            #pragma unroll
            for (int ni = 0; ni < 8; ++ni) {
                int nr = warpN * 64 + ni * 8 + (lane >> 2);
                int c0 = ks * 16 + (lane & 3) * 2;
                unsigned b0 = *(const unsigned*)&sB[st][nr][c0];
                unsigned b1 = *(const unsigned*)&sB[st][nr][c0 + 8];
                mma_f16(acc[0][ni], ah[0], b0, b1);
                mma_f16(acc[1][ni], ah[1], b0, b1);
            }
        }
        __syncthreads();
    }

    // epilogue: store h16 + attention partial dots (head = warpN*4 + ni/2)
    float ps[2][2][4], pd[2][2][4];
    #pragma unroll
    for (int mi = 0; mi < 2; ++mi)
        #pragma unroll
        for (int rh = 0; rh < 2; ++rh)
            #pragma unroll
            for (int hg = 0; hg < 4; ++hg) { ps[mi][rh][hg] = 0.f; pd[mi][rh][hg] = 0.f; }

    #pragma unroll
    for (int ni = 0; ni < 8; ++ni) {
        int cc = warpN * 64 + ni * 8 + (lane & 3) * 2;
        float2 as = *(const float2*)&att_s[cc];
        float2 ad = *(const float2*)&att_d[cc];
        int hg = ni >> 1;
        #pragma unroll
        for (int mi = 0; mi < 2; ++mi) {
            int r0 = rowBase + warpM * 32 + mi * 16 + (lane >> 2);
            int r1 = r0 + 8;
            float x0 = acc[mi][ni][0], x1 = acc[mi][ni][1];
            float x2 = acc[mi][ni][2], x3 = acc[mi][ni][3];
            ps[mi][0][hg] += x0 * as.x + x1 * as.y;
            ps[mi][1][hg] += x2 * as.x + x3 * as.y;
            pd[mi][0][hg] += x0 * ad.x + x1 * ad.y;
            pd[mi][1][hg] += x2 * ad.x + x3 * ad.y;
            if (r0 < NN) *(__half2*)&g_h16[(size_t)r0 * DIM + cc] = __floats2half2_rn(x0, x1);
            if (r1 < NN) *(__half2*)&g_h16[(size_t)r1 * DIM + cc] = __floats2half2_rn(x2, x3);
        }
    }
    #pragma unroll
    for (int o = 1; o < 4; o <<= 1)
        #pragma unroll
        for (int mi = 0; mi < 2; ++mi)
            #pragma unroll
            for (int rh = 0; rh < 2; ++rh)
                #pragma unroll
                for (int hg = 0; hg < 4; ++hg) {
                    ps[mi][rh][hg] += __shfl_xor_sync(0xFFFFFFFFu, ps[mi][rh][hg], o);
                    pd[mi][rh][hg] += __shfl_xor_sync(0xFFFFFFFFu, pd[mi][rh][hg], o);
                }
    if ((lane & 3) == 0) {
        #pragma unroll
        for (int mi = 0; mi < 2; ++mi)
            #pragma unroll
            for (int rh = 0; rh < 2; ++rh) {
                int r = rowBase + warpM * 32 + mi * 16 + (lane >> 2) + rh * 8;
                if (r < NN) {
                    #pragma unroll
                    for (int hg = 0; hg < 4; ++hg) {
                        float s1 = ps[mi][rh][hg];
                        float s2 = pd[mi][rh][hg];
                        g_easrc[r * 8 + warpN * 4 + hg] =
                            make_float2(__expf(s1), __expf(NEG * s1));
                        g_eadst[r * 8 + warpN * 4 + hg] =
                            make_float2(__expf(s2), __expf(NEG * s2));
                    }
                }
            }
    }
}

// -------- FFN1: z = gelu(h1@W1+b1)  (col-tiled) -------------------------------
__global__ __launch_bounds__(256) void k_ffn1t(
    const float* __restrict__ h1, const float* __restrict__ b1)
{
    __shared__ __half sA[2][128][40];
    __shared__ __half sB[2][128][40];

    const int tid  = threadIdx.x;
    const int lane = tid & 31;
    const int wid  = tid >> 5;
    const int warpM = wid & 3;
    const int warpN = wid >> 2;
    const int rowBase = blockIdx.x * 128;
    const int colBase = blockIdx.y * 128;

    auto load_chunk = [&](int c, int st) {
        int k0 = c * 32;
        #pragma unroll
        for (int t = 0; t < 4; ++t) {
            int s = tid + t * 256;
            int m = s >> 3, kq = s & 7;
            int gr = rowBase + m;
            float4 v = (gr < NN) ? *(const float4*)&h1[(size_t)gr * DIM + k0 + kq * 4]
                                 : make_float4(0.f, 0.f, 0.f, 0.f);
            *(__half2*)&sA[st][m][kq * 4]     = __floats2half2_rn(v.x, v.y);
            *(__half2*)&sA[st][m][kq * 4 + 2] = __floats2half2_rn(v.z, v.w);
        }
        #pragma unroll
        for (int t = 0; t < 2; ++t) {
            int s = tid + t * 256;
            int n = s >> 2, ko = (s & 3) * 8;
            cp16(smem_u32(&sB[st][n][ko]),
                 &g_wT[OFF_W1 + (size_t)(colBase + n) * DIM + k0 + ko]);
        }
        cp_commit();
    };

    float acc[2][8][4];
    #pragma unroll
    for (int mi = 0; mi < 2; ++mi)
        #pragma unroll
        for (int ni = 0; ni < 8; ++ni)
            #pragma unroll
            for (int q = 0; q < 4; ++q) acc[mi][ni][q] = 0.f;

    load_chunk(0, 0);
    for (int c = 0; c < 4; ++c) {
        cp_wait0();
        __syncthreads();
        if (c + 1 < 4) load_chunk(c + 1, (c + 1) & 1);
        const int st = c & 1;
        #pragma unroll
        for (int ks = 0; ks < 2; ++ks) {
            unsigned ah[2][4];
            #pragma unroll
            for (int mi = 0; mi < 2; ++mi) {
                int r0 = warpM * 32 + mi * 16 + (lane >> 2);
                int r1 = r0 + 8;
                int c0 = ks * 16 + (lane & 3) * 2;
                ah[mi][0] = *(const unsigned*)&sA[st][r0][c0];
                ah[mi][1] = *(const unsigned*)&sA[st][r1][c0];
                ah[mi][2] = *(const unsigned*)&sA[st][r0][c0 + 8];
                ah[mi][3] = *(const unsigned*)&sA[st][r1][c0 + 8];
            }
            #pragma unroll
            for (int ni = 0; ni < 8; ++ni) {
                int nr = warpN * 64 + ni * 8 + (lane >> 2);
                int c0 = ks * 16 + (lane & 3) * 2;
                unsigned b0 = *(const unsigned*)&sB[st][nr][c0];
                unsigned b1w = *(const unsigned*)&sB[st][nr][c0 + 8];
                mma_f16(acc[0][ni], ah[0], b0, b1w);
                mma_f16(acc[1][ni], ah[1], b0, b1w);
            }
        }
        __syncthreads();
    }

    #pragma unroll
    for (int mi = 0; mi < 2; ++mi) {
        int r0 = rowBase + warpM * 32 + mi * 16 + (lane >> 2);
        int r1 = r0 + 8;
        #pragma unroll
        for (int ni = 0; ni < 8; ++ni) {
            int c = colBase + warpN * 64 + ni * 8 + (lane & 3) * 2;
            float bb0 = b1[c], bb1 = b1[c + 1];
            float x0 = gelu_exact(acc[mi][ni][0] + bb0);
            float x1 = gelu_exact(acc[mi][ni][1] + bb1);
            float x2 = gelu_exact(acc[mi][ni][2] + bb0);
            float x3 = gelu_exact(acc[mi][ni][3] + bb1);
            if (r0 < NN) *(__half2*)&g_z[(size_t)r0 * HID + c] = __floats2half2_rn(x0, x1);
            if (r1 < NN) *(__half2*)&g_z[(size_t)r1 * HID + c] = __floats2half2_rn(x2, x3);
        }
    }
}

// -------- FFN2 + residual + LN2: io = LN(io + z@W2 + b2) ---------------------
__global__ __launch_bounds__(256) void k_ffn2t(
    const float* __restrict__ b2,
    const float* __restrict__ gamma, const float* __restrict__ beta,
    float* __restrict__ io)
{
    __shared__ __half sA[2][128][40];
    __shared__ __half sB[2][128][40];
    __shared__ float  redS[2][128];
    __shared__ float  redQ[2][128];

    const int tid  = threadIdx.x;
    const int lane = tid & 31;
    const int wid  = tid >> 5;
    const int warpM = wid & 3;
    const int warpN = wid >> 2;
    const int rowBase = blockIdx.x * 128;

    auto load_chunk = [&](int c, int st) {
        int k0 = c * 32;
        #pragma unroll
        for (int t = 0; t < 2; ++t) {
            int s = tid + t * 256;
            int m = s >> 2, ko = (s & 3) * 8;
            int gr = rowBase + m;
            const __half* gp = &g_z[(size_t)(gr < NN ? gr : 0) * HID + k0 + ko];
            cp16(smem_u32(&sA[st][m][ko]), gp);
        }
        #pragma unroll
        for (int t = 0; t < 2; ++t) {
            int s = tid + t * 256;
            int n = s >> 2, ko = (s & 3) * 8;
            cp16(smem_u32(&sB[st][n][ko]),
                 &g_wT[OFF_W2 + (size_t)n * HID + k0 + ko]);
        }
        cp_commit();
    };

    float acc[2][8][4];
    #pragma unroll
    for (int mi = 0; mi < 2; ++mi)
        #pragma unroll
        for (int ni = 0; ni < 8; ++ni)
            #pragma unroll
            for (int q = 0; q < 4; ++q) acc[mi][ni][q] = 0.f;

    load_chunk(0, 0);
    for (int c = 0; c < 16; ++c) {
        cp_wait0();
        __syncthreads();
        if (c + 1 < 16) load_chunk(c + 1, (c + 1) & 1);
        const int st = c & 1;
        #pragma unroll
        for (int ks = 0; ks < 2; ++ks) {
            unsigned ah[2][4];
            #pragma unroll
            for (int mi = 0; mi < 2; ++mi) {
                int r0 = warpM * 32 + mi * 16 + (lane >> 2);
                int r1 = r0 + 8;
                int c0 = ks * 16 + (lane & 3) * 2;
                ah[mi][0] = *(const unsigned*)&sA[st][r0][c0];
                ah[mi][1] = *(const unsigned*)&sA[st][r1][c0];
                ah[mi][2] = *(const unsigned*)&sA[st][r0][c0 + 8];
                ah[mi][3] = *(const unsigned*)&sA[st][r1][c0 + 8];
            }
            #pragma unroll
            for (int ni = 0; ni < 8; ++ni) {
                int nr = warpN * 64 + ni * 8 + (lane >> 2);
                int c0 = ks * 16 + (lane & 3) * 2;
                unsigned b0 = *(const unsigned*)&sB[st][nr][c0];
                unsigned b1w = *(const unsigned*)&sB[st][nr][c0 + 8];
                mma_f16(acc[0][ni], ah[0], b0, b1w);
                mma_f16(acc[1][ni], ah[1], b0, b1w);
            }
        }
        __syncthreads();
    }

    float sS[2][2] = {{0.f, 0.f}, {0.f, 0.f}};
    float sQ[2][2] = {{0.f, 0.f}, {0.f, 0.f}};
    #pragma unroll
    for (int mi = 0; mi < 2; ++mi) {
        int r0 = rowBase + warpM * 32 + mi * 16 + (lane >> 2);
        int r1 = r0 + 8;
        #pragma unroll
        for (int ni = 0; ni < 8; ++ni) {
            int c = warpN * 64 + ni * 8 + (lane & 3) * 2;
            float bb0 = b2[c], bb1 = b2[c + 1];
            float2 i0 = (r0 < NN) ? *(const float2*)&io[(size_t)r0 * DIM + c]
                                  : make_float2(0.f, 0.f);
            float2 i1 = (r1 < NN) ? *(const float2*)&io[(size_t)r1 * DIM + c]
                                  : make_float2(0.f, 0.f);
            float v0 = acc[mi][ni][0] + bb0 + i0.x;
            float v1 = acc[mi][ni][1] + bb1 + i0.y;
            float v2 = acc[mi][ni][2] + bb0 + i1.x;
            float v3 = acc[mi][ni][3] + bb1 + i1.y;
            acc[mi][ni][0] = v0; acc[mi][ni][1] = v1;
            acc[mi][ni][2] = v2; acc[mi][ni][3] = v3;
            sS[mi][0] += v0 + v1;       sS[mi][1] += v2 + v3;
            sQ[mi][0] += v0*v0 + v1*v1; sQ[mi][1] += v2*v2 + v3*v3;
        }
    }
    #pragma unroll
    for (int mi = 0; mi < 2; ++mi)
        #pragma unroll
        for (int k = 0; k < 2; ++k)
            #pragma unroll
            for (int o = 1; o < 4; o <<= 1) {
                sS[mi][k] += __shfl_xor_sync(0xFFFFFFFFu, sS[mi][k], o);
                sQ[mi][k] += __shfl_xor_sync(0xFFFFFFFFu, sQ[mi][k], o);
            }
    if ((lane & 3) == 0) {
        #pragma unroll
        for (int mi = 0; mi < 2; ++mi) {
            int lr = warpM * 32 + mi * 16 + (lane >> 2);
            redS[warpN][lr]     = sS[mi][0];
            redS[warpN][lr + 8] = sS[mi][1];
            redQ[warpN][lr]     = sQ[mi][0];
            redQ[warpN][lr + 8] = sQ[mi][1];
        }
    }
    __syncthreads();
    #pragma unroll
    for (int mi = 0; mi < 2; ++mi) {
        int lr0 = warpM * 32 + mi * 16 + (lane >> 2);
        int lr1 = lr0 + 8;
        float S0 = redS[0][lr0] + redS[1][lr0];
        float S1 = redS[0][lr1] + redS[1][lr1];
        float Q0 = redQ[0][lr0] + redQ[1][lr0];
        float Q1 = redQ[0][lr1] + redQ[1][lr1];
        float mu0 = S0 * (1.f / DIM), mu1 = S1 * (1.f / DIM);
        float rs0 = rsqrtf(fmaxf(Q0 * (1.f / DIM) - mu0 * mu0, 0.f) + LNEPS);
        float rs1 = rsqrtf(fmaxf(Q1 * (1.f / DIM) - mu1 * mu1, 0.f) + LNEPS);
        int r0 = rowBase + lr0;
        int r1 = rowBase + lr1;
        #pragma unroll
        for (int ni = 0; ni < 8; ++ni) {
            int c = warpN * 64 + ni * 8 + (lane & 3) * 2;
            float2 gv = *(const float2*)&gamma[c];
            float2 bv = *(const float2*)&beta[c];
            if (r0 < NN) {
                float2 o0;
                o0.x = gv.x * (acc[mi][ni][0] - mu0) * rs0 + bv.x;
                o0.y = gv.y * (acc[mi][ni][1] - mu0) * rs0 + bv.y;
                *(float2*)&io[(size_t)r0 * DIM + c] = o0;
            }
            if (r1 < NN) {
                float2 o1;
                o1.x = gv.x * (acc[mi][ni][2] - mu1) * rs1 + bv.x;
                o1.y = gv.y * (acc[mi][ni][3] - mu1) * rs1 + bv.y;
                *(float2*)&io[(size_t)r1 * DIM + c] = o1;
            }
        }
    }
}

// -------- aggregation + residual + LN1, exp-free edge weights ----------------
// p(edge) = exp(leaky(a_src+a_dst)) = max(E1s*E1d, E2s*E2d)  -- no MUFU/edge.
__global__ __launch_bounds__(256) void k_agg_ln(
    const float* __restrict__ x, const float* __restrict__ bg,
    const float* __restrict__ gamma, const float* __restrict__ beta,
    float* __restrict__ h1)
{
    int w = (blockIdx.x * blockDim.x + threadIdx.x) >> 5;
    if (w >= NN) return;
    const int lane = threadIdx.x & 31;
    const int myh = lane >> 2;

    const float2 ed = g_eadst[w * 8 + myh];     // (E1d, E2d)

    const int beg = g_offsets[w];
    const int end = g_offsets[w + 1];

    float l = 0.f;
    float a0 = 0.f, a1 = 0.f, a2 = 0.f, a3 = 0.f;
    {   // self loop
        float2 es = g_easrc[w * 8 + myh];
        float p = fmaxf(es.x * ed.x, es.y * ed.y);
        l += p;
        uint2 u = *(const uint2*)&g_h16[(size_t)w * DIM + lane * 4];
        float2 h0 = __half22float2(*(__half2*)&u.x);
        float2 h1v = __half22float2(*(__half2*)&u.y);
        a0 += p * h0.x; a1 += p * h0.y; a2 += p * h1v.x; a3 += p * h1v.y;
    }
    int j = beg;
    for (; j + 3 < end; j += 4) {
        int s0 = g_csr[j],     s1 = g_csr[j + 1];
        int s2 = g_csr[j + 2], s3 = g_csr[j + 3];
        float2 e0 = g_easrc[s0 * 8 + myh];
        float2 e1 = g_easrc[s1 * 8 + myh];
        float2 e2 = g_easrc[s2 * 8 + myh];
        float2 e3 = g_easrc[s3 * 8 + myh];
        float p0 = fmaxf(e0.x * ed.x, e0.y * ed.y);
        float p1 = fmaxf(e1.x * ed.x, e1.y * ed.y);
        float p2 = fmaxf(e2.x * ed.x, e2.y * ed.y);
        float p3 = fmaxf(e3.x * ed.x, e3.y * ed.y);
        uint2 u0 = *(const uint2*)&g_h16[(size_t)s0 * DIM + lane * 4];
        uint2 u1 = *(const uint2*)&g_h16[(size_t)s1 * DIM + lane * 4];
        uint2 u2 = *(const uint2*)&g_h16[(size_t)s2 * DIM + lane * 4];
        uint2 u3 = *(const uint2*)&g_h16[(size_t)s3 * DIM + lane * 4];
        l += p0 + p1 + p2 + p3;
        float2 q0 = __half22float2(*(__half2*)&u0.x);
        float2 q1 = __half22float2(*(__half2*)&u0.y);
        float2 r0 = __half22float2(*(__half2*)&u1.x);
        float2 r1 = __half22float2(*(__half2*)&u1.y);
        float2 t0 = __half22float2(*(__half2*)&u2.x);
        float2 t1 = __half22float2(*(__half2*)&u2.y);
        float2 v0 = __half22float2(*(__half2*)&u3.x);
        float2 v1 = __half22float2(*(__half2*)&u3.y);
        a0 += p0 * q0.x + p1 * r0.x + p2 * t0.x + p3 * v0.x;
        a1 += p0 * q0.y + p1 * r0.y + p2 * t0.y + p3 * v0.y;
        a2 += p0 * q1.x + p1 * r1.x + p2 * t1.x + p3 * v1.x;
        a3 += p0 * q1.y + p1 * r1.y + p2 * t1.y + p3 * v1.y;
    }
    for (; j < end; ++j) {
        int s = g_csr[j];
        float2 es = g_easrc[s * 8 + myh];
        float p = fmaxf(es.x * ed.x, es.y * ed.y);
        l += p;
        uint2 u = *(const uint2*)&g_h16[(size_t)s * DIM + lane * 4];
        float2 h0 = __half22float2(*(__half2*)&u.x);
        float2 h1v = __half22float2(*(__half2*)&u.y);
        a0 += p * h0.x; a1 += p * h0.y; a2 += p * h1v.x; a3 += p * h1v.y;
    }
    float inv = 1.f / (l + 1e-16f);

    float4 xv  = *(const float4*)&x[(size_t)w * DIM + lane * 4];
    float4 bgv = *(const float4*)&bg[lane * 4];
    float4 v;
    v.x = xv.x + a0 * inv + bgv.x;
    v.y = xv.y + a1 * inv + bgv.y;
    v.z = xv.z + a2 * inv + bgv.z;
    v.w = xv.w + a3 * inv + bgv.w;

    float s = v.x + v.y + v.z + v.w;
    #pragma unroll
    for (int o = 16; o > 0; o >>= 1) s += __shfl_xor_sync(0xFFFFFFFFu, s, o);
    float mu = s * (1.f / DIM);
    v.x -= mu; v.y -= mu; v.z -= mu; v.w -= mu;
    float q = v.x * v.x + v.y * v.y + v.z * v.z + v.w * v.w;
    #pragma unroll
    for (int o = 16; o > 0; o >>= 1) q += __shfl_xor_sync(0xFFFFFFFFu, q, o);
    float rs = rsqrtf(q * (1.f / DIM) + LNEPS);
    float4 g  = *(const float4*)&gamma[lane * 4];
    float4 be = *(const float4*)&beta[lane * 4];
    float4 o4;
    o4.x = g.x * v.x * rs + be.x;
    o4.y = g.y * v.y * rs + be.y;
    o4.z = g.z * v.z * rs + be.z;
    o4.w = g.w * v.w * rs + be.w;
    *(float4*)&h1[(size_t)w * DIM + lane * 4] = o4;
}

// ---------------- launcher: forked capture branches ---------------------------
extern "C" void kernel_launch(void* const* d_in, const int* in_sizes, int n_in,
                              void* d_out, int out_size)
{
    const float* x     = (const float*)d_in[0];
    const void*  ei    = d_in[1];
    const float* Wg    = (const float*)d_in[2];
    const float* att_s = (const float*)d_in[3];
    const float* att_d = (const float*)d_in[4];
    const float* bg    = (const float*)d_in[5];
    const float* gamma = (const float*)d_in[6];
    const float* beta  = (const float*)d_in[7];
    const float* W1    = (const float*)d_in[8];
    const float* b1    = (const float*)d_in[9];
    const float* W2    = (const float*)d_in[10];
    const float* b2    = (const float*)d_in[11];
    float*       out   = (float*)d_out;

    cudaStream_t sB;
    cudaStreamCreateWithFlags(&sB, cudaStreamNonBlocking);
    cudaEvent_t evFork, evJoin;
    cudaEventCreateWithFlags(&evFork, cudaEventDisableTiming);
    cudaEventCreateWithFlags(&evJoin, cudaEventDisableTiming);

    cudaEventRecord(evFork, 0);
    cudaStreamWaitEvent(sB, evFork, 0);

    // Branch A (main stream): edge/CSR pipeline
    k_prep<<<(NN + 255) / 256, 256>>>((const unsigned int*)ei);
    k_hist<<<(NE + 255) / 256, 256>>>(ei);
    k_scan_part<<<SCAN_NB, 1024>>>();
    k_scan_tops<<<1, 128>>>();
    k_scan_add<<<SCAN_NB, 1024>>>();
    k_scatter<<<(NE + 255) / 256, 256>>>(ei);

    // Branch B (side stream): weights + gemm1 (+attn exp forms fused)
    k_convT_all<<<(WTOT + 255) / 256, 256, 0, sB>>>(Wg, W1, W2);
    k_gemm1<<<GB_ROWS, 256, 0, sB>>>(x, att_s, att_d);

    cudaEventRecord(evJoin, sB);
    cudaStreamWaitEvent(0, evJoin, 0);

    // Joined tail
    k_agg_ln<<<(NN * 32 + 255) / 256, 256>>>(x, bg, gamma, beta, out);
    k_ffn1t<<<dim3(GB_ROWS, HID / 128), 256>>>(out, b1);
    k_ffn2t<<<GB_ROWS, 256>>>(b2, gamma, beta, out);
}

// round 15
// speedup vs baseline: 1.0553x; 1.0382x over previous
#include <cuda_runtime.h>
#include <cuda_fp16.h>
#include <math.h>

#define NN    100000
#define DIM   128
#define HEADS 8
#define NE    1600000
#define NEG   0.2f
#define LNEPS 1e-5f
#define HID   512
#define GB_ROWS 782            // ceil(NN/128)
#define SCAN_NB 98             // ceil(NN/1024)

#define OFF_WG 0
#define OFF_W1 16384           // 128*128
#define OFF_W2 81920           // + 128*512
#define WTOT   147456          // + 512*128

// ---------------- scratch (static device globals; no allocation) -------------
__device__ __half g_h16 [(size_t)NN * DIM];   // x@Wg (fp16)
__device__ __half g_z   [(size_t)NN * HID];   // FFN hidden (fp16)
__device__ float  g_asrc[NN * HEADS];
__device__ float  g_adst[NN * HEADS];
__device__ __half g_wT  [WTOT];               // W^T fp16 [n][k]
__device__ int    g_counts  [NN];
__device__ int    g_rank    [NE];             // edge rank within dst bucket
__device__ int    g_offsets [NN + 1];
__device__ int    g_csr     [NE];
__device__ int    g_blocksum[SCAN_NB];
__device__ int    g_blockoff[SCAN_NB];
__device__ int    g_is64;

// ---------------- prep: zero counters + edge dtype detection ------------------
__global__ void k_prep(const unsigned int* __restrict__ ew) {
    int i = blockIdx.x * blockDim.x + threadIdx.x;
    if (i < NN) g_counts[i] = 0;
    if (i == 0) {
        unsigned int acc = 0;
        #pragma unroll
        for (int t = 0; t < 16; ++t) acc |= ew[2 * t + 1];
        g_is64 = (acc == 0) ? 1 : 0;
    }
}

__device__ __forceinline__ int edge_at(const void* ei, int is64, size_t idx) {
    if (is64) return (int)((const long long*)ei)[idx];
    return ((const int*)ei)[idx];
}

// hist also records each edge's rank within its destination bucket
__global__ void k_hist(const void* __restrict__ ei) {
    int i = blockIdx.x * blockDim.x + threadIdx.x;
    if (i >= NE) return;
    int dst = edge_at(ei, g_is64, (size_t)NE + i);
    if ((unsigned)dst < (unsigned)NN)
        g_rank[i] = atomicAdd(&g_counts[dst], 1);
}

__global__ __launch_bounds__(1024) void k_scan_part() {
    __shared__ int ws[32];
    int tid = threadIdx.x;
    int i = blockIdx.x * 1024 + tid;
    int v = (i < NN) ? g_counts[i] : 0;
    int lane = tid & 31, wid = tid >> 5;
    int x = v;
    #pragma unroll
    for (int o = 1; o < 32; o <<= 1) {
        int y = __shfl_up_sync(0xFFFFFFFFu, x, o);
        if (lane >= o) x += y;
    }
    if (lane == 31) ws[wid] = x;
    __syncthreads();
    if (wid == 0) {
        int s = ws[lane];
        #pragma unroll
        for (int o = 1; o < 32; o <<= 1) {
            int y = __shfl_up_sync(0xFFFFFFFFu, s, o);
            if (lane >= o) s += y;
        }
        ws[lane] = s;
    }
    __syncthreads();
    int base = wid ? ws[wid - 1] : 0;
    int incl = base + x;
    if (i < NN) g_offsets[i] = incl - v;
    if (tid == 1023) g_blocksum[blockIdx.x] = incl;
}

__global__ void k_scan_tops() {
    __shared__ int ws[4];
    int t = threadIdx.x;
    int v = (t < SCAN_NB) ? g_blocksum[t] : 0;
    int lane = t & 31, wid = t >> 5;
    int x = v;
    #pragma unroll
    for (int o = 1; o < 32; o <<= 1) {
        int y = __shfl_up_sync(0xFFFFFFFFu, x, o);
        if (lane >= o) x += y;
    }
    if (lane == 31) ws[wid] = x;
    __syncthreads();
    int add = 0;
    for (int w = 0; w < wid; ++w) add += ws[w];
    x += add;
    if (t < SCAN_NB) g_blockoff[t] = x - v;
    if (t == SCAN_NB - 1) g_offsets[NN] = x;
}

__global__ __launch_bounds__(1024) void k_scan_add() {
    int i = blockIdx.x * 1024 + threadIdx.x;
    if (i < NN) g_offsets[i] += g_blockoff[blockIdx.x];
}

// scatter: pure load/store, no atomics (rank precomputed in hist)
__global__ void k_scatter(const void* __restrict__ ei) {
    int i = blockIdx.x * blockDim.x + threadIdx.x;
    if (i >= NE) return;
    int src = edge_at(ei, g_is64, i);
    int dst = edge_at(ei, g_is64, (size_t)NE + i);
    if ((unsigned)src < (unsigned)NN && (unsigned)dst < (unsigned)NN)
        g_csr[g_offsets[dst] + g_rank[i]] = src;
}

// -------- all-weights convert+transpose (fp32 [k][n] -> fp16 [n][k]) ----------
__global__ void k_convT_all(const float* __restrict__ Wg,
                            const float* __restrict__ W1,
                            const float* __restrict__ W2) {
    int i = blockIdx.x * blockDim.x + threadIdx.x;
    if (i >= WTOT) return;
    const float* src; int K, N, off, loc;
    if (i < OFF_W1)      { src = Wg; K = DIM; N = DIM; off = OFF_WG; loc = i; }
    else if (i < OFF_W2) { src = W1; K = DIM; N = HID; off = OFF_W1; loc = i - OFF_W1; }
    else                 { src = W2; K = HID; N = DIM; off = OFF_W2; loc = i - OFF_W2; }
    int k = loc / N, n = loc % N;
    g_wT[off + n * K + k] = __float2half_rn(src[loc]);
}

// ---------------- pipelined fp16 tensor-core GEMM ----------------------------
__device__ __forceinline__ void mma_f16(float* c, const unsigned* a,
                                        unsigned b0, unsigned b1) {
    asm volatile(
        "mma.sync.aligned.m16n8k16.row.col.f32.f16.f16.f32 "
        "{%0,%1,%2,%3}, {%4,%5,%6,%7}, {%8,%9}, {%0,%1,%2,%3};"
        : "+f"(c[0]), "+f"(c[1]), "+f"(c[2]), "+f"(c[3])
        : "r"(a[0]), "r"(a[1]), "r"(a[2]), "r"(a[3]), "r"(b0), "r"(b1));
}
__device__ __forceinline__ unsigned smem_u32(const void* p) {
    return (unsigned)__cvta_generic_to_shared(p);
}
__device__ __forceinline__ void cp16(unsigned dst, const void* src) {
    asm volatile("cp.async.cg.shared.global [%0], [%1], 16;"
                 :: "r"(dst), "l"(src));
}
__device__ __forceinline__ void cp_commit() {
    asm volatile("cp.async.commit_group;");
}
__device__ __forceinline__ void cp_wait0() {
    asm volatile("cp.async.wait_group 0;");
}
__device__ __forceinline__ float gelu_exact(float t) {
    return 0.5f * t * (1.0f + erff(t * 0.70710678118654752f));
}

// EPI: 0 = plain fp16 store; 1 = bias+gelu fp16 store; 2 = bias+residual+LN2
template<bool A_HALF, int EPI>
__device__ __forceinline__ void gemm_body(
    const void* __restrict__ Ap,
    const __half* __restrict__ BT,
    const float* __restrict__ bias,
    __half* __restrict__ Ch,
    float* __restrict__ io,
    const float* __restrict__ gamma, const float* __restrict__ beta,
    int M, int N, int K, int rowTile, int colTile)
{
    __shared__ __half sA[2][128][40];
    __shared__ __half sB[2][128][40];
    __shared__ float  redS[2][128];
    __shared__ float  redQ[2][128];

    const int tid  = threadIdx.x;
    const int lane = tid & 31;
    const int wid  = tid >> 5;
    const int warpM = wid & 3;
    const int warpN = wid >> 2;
    const int rowBase = rowTile * 128;
    const int colBase = colTile * 128;
    const int nc = K >> 5;                   // KC = 32

    auto load_chunk = [&](int c, int st) {
        int k0 = c * 32;
        if (A_HALF) {
            const __half* A = (const __half*)Ap;
            #pragma unroll
            for (int t = 0; t < 2; ++t) {
                int s = tid + t * 256;
                int m = s >> 2, ko = (s & 3) * 8;
                int gr = rowBase + m;
                const void* gp = &A[(size_t)(gr < M ? gr : 0) * K + k0 + ko];
                cp16(smem_u32(&sA[st][m][ko]), gp);
            }
        } else {
            const float* A = (const float*)Ap;
            #pragma unroll
            for (int t = 0; t < 4; ++t) {
                int s = tid + t * 256;
                int m = s >> 3, kq = s & 7;
                int gr = rowBase + m;
                float4 v = (gr < M) ? *(const float4*)&A[(size_t)gr * K + k0 + kq * 4]
                                    : make_float4(0.f, 0.f, 0.f, 0.f);
                *(__half2*)&sA[st][m][kq * 4]     = __floats2half2_rn(v.x, v.y);
                *(__half2*)&sA[st][m][kq * 4 + 2] = __floats2half2_rn(v.z, v.w);
            }
        }
        #pragma unroll
        for (int t = 0; t < 2; ++t) {
            int s = tid + t * 256;
            int n = s >> 2, ko = (s & 3) * 8;
            cp16(smem_u32(&sB[st][n][ko]),
                 &BT[(size_t)(colBase + n) * K + k0 + ko]);
        }
        cp_commit();
    };

    float acc[2][8][4];
    #pragma unroll
    for (int mi = 0; mi < 2; ++mi)
        #pragma unroll
        for (int ni = 0; ni < 8; ++ni)
            #pragma unroll
            for (int q = 0; q < 4; ++q) acc[mi][ni][q] = 0.f;

    load_chunk(0, 0);
    for (int c = 0; c < nc; ++c) {
        cp_wait0();
        __syncthreads();
        if (c + 1 < nc) load_chunk(c + 1, (c + 1) & 1);
        const int st = c & 1;

        #pragma unroll
        for (int ks = 0; ks < 2; ++ks) {
            unsigned ah[2][4];
            #pragma unroll
            for (int mi = 0; mi < 2; ++mi) {
                int r0 = warpM * 32 + mi * 16 + (lane >> 2);
                int r1 = r0 + 8;
                int c0 = ks * 16 + (lane & 3) * 2;
                int c1 = c0 + 8;
                ah[mi][0] = *(const unsigned*)&sA[st][r0][c0];
                ah[mi][1] = *(const unsigned*)&sA[st][r1][c0];
                ah[mi][2] = *(const unsigned*)&sA[st][r0][c1];
                ah[mi][3] = *(const unsigned*)&sA[st][r1][c1];
            }
            #pragma unroll
            for (int ni = 0; ni < 8; ++ni) {
                int nr = warpN * 64 + ni * 8 + (lane >> 2);
                int c0 = ks * 16 + (lane & 3) * 2;
                unsigned b0 = *(const unsigned*)&sB[st][nr][c0];
                unsigned b1 = *(const unsigned*)&sB[st][nr][c0 + 8];
                mma_f16(acc[0][ni], ah[0], b0, b1);
                mma_f16(acc[1][ni], ah[1], b0, b1);
            }
        }
        __syncthreads();
    }

    if (EPI == 0 || EPI == 1) {
        #pragma unroll
        for (int mi = 0; mi < 2; ++mi) {
            int r0 = rowBase + warpM * 32 + mi * 16 + (lane >> 2);
            int r1 = r0 + 8;
            #pragma unroll
            for (int ni = 0; ni < 8; ++ni) {
                int c = colBase + warpN * 64 + ni * 8 + (lane & 3) * 2;
                float b0 = 0.f, b1v = 0.f;
                if (EPI == 1) { b0 = bias[c]; b1v = bias[c + 1]; }
                float x0 = acc[mi][ni][0] + b0, x1 = acc[mi][ni][1] + b1v;
                float x2 = acc[mi][ni][2] + b0, x3 = acc[mi][ni][3] + b1v;
                if (EPI == 1) {
                    x0 = gelu_exact(x0); x1 = gelu_exact(x1);
                    x2 = gelu_exact(x2); x3 = gelu_exact(x3);
                }
                if (r0 < M) *(__half2*)&Ch[(size_t)r0 * N + c] = __floats2half2_rn(x0, x1);
                if (r1 < M) *(__half2*)&Ch[(size_t)r1 * N + c] = __floats2half2_rn(x2, x3);
            }
        }
    } else {
        float sS[2][2] = {{0.f, 0.f}, {0.f, 0.f}};
        float sQ[2][2] = {{0.f, 0.f}, {0.f, 0.f}};
        #pragma unroll
        for (int mi = 0; mi < 2; ++mi) {
            int r0 = rowBase + warpM * 32 + mi * 16 + (lane >> 2);
            int r1 = r0 + 8;
            #pragma unroll
            for (int ni = 0; ni < 8; ++ni) {
                int c = warpN * 64 + ni * 8 + (lane & 3) * 2;
                float bb0 = bias[c], bb1 = bias[c + 1];
                float2 i0 = (r0 < M) ? *(const float2*)&io[(size_t)r0 * N + c]
                                     : make_float2(0.f, 0.f);
                float2 i1 = (r1 < M) ? *(const float2*)&io[(size_t)r1 * N + c]
                                     : make_float2(0.f, 0.f);
                float v0 = acc[mi][ni][0] + bb0 + i0.x;
                float v1 = acc[mi][ni][1] + bb1 + i0.y;
                float v2 = acc[mi][ni][2] + bb0 + i1.x;
                float v3 = acc[mi][ni][3] + bb1 + i1.y;
                acc[mi][ni][0] = v0; acc[mi][ni][1] = v1;
                acc[mi][ni][2] = v2; acc[mi][ni][3] = v3;
                sS[mi][0] += v0 + v1;       sS[mi][1] += v2 + v3;
                sQ[mi][0] += v0*v0 + v1*v1; sQ[mi][1] += v2*v2 + v3*v3;
            }
        }
        #pragma unroll
        for (int mi = 0; mi < 2; ++mi)
            #pragma unroll
            for (int k = 0; k < 2; ++k)
                #pragma unroll
                for (int o = 1; o < 4; o <<= 1) {
                    sS[mi][k] += __shfl_xor_sync(0xFFFFFFFFu, sS[mi][k], o);
                    sQ[mi][k] += __shfl_xor_sync(0xFFFFFFFFu, sQ[mi][k], o);
                }
        if ((lane & 3) == 0) {
            #pragma unroll
            for (int mi = 0; mi < 2; ++mi) {
                int lr = warpM * 32 + mi * 16 + (lane >> 2);
                redS[warpN][lr]     = sS[mi][0];
                redS[warpN][lr + 8] = sS[mi][1];
                redQ[warpN][lr]     = sQ[mi][0];
                redQ[warpN][lr + 8] = sQ[mi][1];
            }
        }
        __syncthreads();
        #pragma unroll
        for (int mi = 0; mi < 2; ++mi) {
            int lr0 = warpM * 32 + mi * 16 + (lane >> 2);
            int lr1 = lr0 + 8;
            float S0 = redS[0][lr0] + redS[1][lr0];
            float S1 = redS[0][lr1] + redS[1][lr1];
            float Q0 = redQ[0][lr0] + redQ[1][lr0];
            float Q1 = redQ[0][lr1] + redQ[1][lr1];
            float mu0 = S0 * (1.f / DIM), mu1 = S1 * (1.f / DIM);
            float rs0 = rsqrtf(fmaxf(Q0 * (1.f / DIM) - mu0 * mu0, 0.f) + LNEPS);
            float rs1 = rsqrtf(fmaxf(Q1 * (1.f / DIM) - mu1 * mu1, 0.f) + LNEPS);
            int r0 = rowBase + lr0;
            int r1 = rowBase + lr1;
            #pragma unroll
            for (int ni = 0; ni < 8; ++ni) {
                int c = warpN * 64 + ni * 8 + (lane & 3) * 2;
                float2 gv = *(const float2*)&gamma[c];
                float2 bv = *(const float2*)&beta[c];
                if (r0 < M) {
                    float2 o0;
                    o0.x = gv.x * (acc[mi][ni][0] - mu0) * rs0 + bv.x;
                    o0.y = gv.y * (acc[mi][ni][1] - mu0) * rs0 + bv.y;
                    *(float2*)&io[(size_t)r0 * N + c] = o0;
                }
                if (r1 < M) {
                    float2 o1;
                    o1.x = gv.x * (acc[mi][ni][2] - mu1) * rs1 + bv.x;
                    o1.y = gv.y * (acc[mi][ni][3] - mu1) * rs1 + bv.y;
                    *(float2*)&io[(size_t)r1 * N + c] = o1;
                }
            }
        }
    }
}

__global__ __launch_bounds__(256) void k_gemm1(const float* __restrict__ x) {
    gemm_body<false, 0>(x, g_wT + OFF_WG, nullptr, g_h16, nullptr,
                        nullptr, nullptr, NN, DIM, DIM, blockIdx.x, 0);
}
__global__ __launch_bounds__(256) void k_ffn1t(const float* __restrict__ h1,
                                               const float* __restrict__ b1) {
    gemm_body<false, 1>(h1, g_wT + OFF_W1, b1, g_z, nullptr,
                        nullptr, nullptr, NN, HID, DIM, blockIdx.x, blockIdx.y);
}
__global__ __launch_bounds__(256) void k_ffn2t(const float* __restrict__ b2,
                                               const float* __restrict__ gamma,
                                               const float* __restrict__ beta,
                                               float* __restrict__ io) {
    gemm_body<true, 2>(g_z, g_wT + OFF_W2, b2, nullptr, io,
                       gamma, beta, NN, DIM, HID, blockIdx.x, 0);
}

// ---------------- attention coefficients (fp16 h) -----------------------------
__global__ void k_attn(const float* __restrict__ att_s,
                       const float* __restrict__ att_d) {
    int idx = blockIdx.x * blockDim.x + threadIdx.x;
    if (idx >= NN * HEADS) return;
    int n = idx >> 3, hh = idx & 7;
    const __half* hr = &g_h16[(size_t)n * DIM + hh * 16];
    float s1 = 0.f, s2 = 0.f;
    #pragma unroll
    for (int k = 0; k < 8; ++k) {
        float2 hv = __half22float2(*(const __half2*)&hr[k * 2]);
        s1 = fmaf(hv.x, att_s[hh * 16 + k * 2],     s1);
        s1 = fmaf(hv.y, att_s[hh * 16 + k * 2 + 1], s1);
        s2 = fmaf(hv.x, att_d[hh * 16 + k * 2],     s2);
        s2 = fmaf(hv.y, att_d[hh * 16 + k * 2 + 1], s2);
    }
    g_asrc[idx] = s1;
    g_adst[idx] = s2;
}

// -------- single-pass aggregation + residual + LN1 (1 warp / node) -----------
__device__ __forceinline__ float leaky(float v) { return fmaxf(v, NEG * v); }

__global__ __launch_bounds__(256) void k_agg_ln(
    const float* __restrict__ x, const float* __restrict__ bg,
    const float* __restrict__ gamma, const float* __restrict__ beta,
    float* __restrict__ h1)
{
    int w = (blockIdx.x * blockDim.x + threadIdx.x) >> 5;
    if (w >= NN) return;
    const int lane = threadIdx.x & 31;
    const int myh = lane >> 2;

    const float adm  = g_adst[w * 8 + myh];
    const float asm_ = g_asrc[w * 8 + myh];

    const int beg = g_offsets[w];
    const int end = g_offsets[w + 1];

    float l = 0.f;
    float a0 = 0.f, a1 = 0.f, a2 = 0.f, a3 = 0.f;
    {   // self loop
        float p = __expf(leaky(asm_ + adm));
        l += p;
        uint2 u = *(const uint2*)&g_h16[(size_t)w * DIM + lane * 4];
        float2 h0 = __half22float2(*(__half2*)&u.x);
        float2 h1v = __half22float2(*(__half2*)&u.y);
        a0 += p * h0.x; a1 += p * h0.y; a2 += p * h1v.x; a3 += p * h1v.y;
    }
    int j = beg;
    for (; j + 3 < end; j += 4) {
        int s0 = g_csr[j],     s1 = g_csr[j + 1];
        int s2 = g_csr[j + 2], s3 = g_csr[j + 3];
        float p0 = __expf(leaky(g_asrc[s0 * 8 + myh] + adm));
        float p1 = __expf(leaky(g_asrc[s1 * 8 + myh] + adm));
        float p2 = __expf(leaky(g_asrc[s2 * 8 + myh] + adm));
        float p3 = __expf(leaky(g_asrc[s3 * 8 + myh] + adm));
        uint2 u0 = *(const uint2*)&g_h16[(size_t)s0 * DIM + lane * 4];
        uint2 u1 = *(const uint2*)&g_h16[(size_t)s1 * DIM + lane * 4];
        uint2 u2 = *(const uint2*)&g_h16[(size_t)s2 * DIM + lane * 4];
        uint2 u3 = *(const uint2*)&g_h16[(size_t)s3 * DIM + lane * 4];
        l += p0 + p1 + p2 + p3;
        float2 q0 = __half22float2(*(__half2*)&u0.x);
        float2 q1 = __half22float2(*(__half2*)&u0.y);
        float2 r0 = __half22float2(*(__half2*)&u1.x);
        float2 r1 = __half22float2(*(__half2*)&u1.y);
        float2 t0 = __half22float2(*(__half2*)&u2.x);
        float2 t1 = __half22float2(*(__half2*)&u2.y);
        float2 v0 = __half22float2(*(__half2*)&u3.x);
        float2 v1 = __half22float2(*(__half2*)&u3.y);
        a0 += p0 * q0.x + p1 * r0.x + p2 * t0.x + p3 * v0.x;
        a1 += p0 * q0.y + p1 * r0.y + p2 * t0.y + p3 * v0.y;
        a2 += p0 * q1.x + p1 * r1.x + p2 * t1.x + p3 * v1.x;
        a3 += p0 * q1.y + p1 * r1.y + p2 * t1.y + p3 * v1.y;
    }
    for (; j < end; ++j) {
        int s = g_csr[j];
        float p = __expf(leaky(g_asrc[s * 8 + myh] + adm));
        l += p;
        uint2 u = *(const uint2*)&g_h16[(size_t)s * DIM + lane * 4];
        float2 h0 = __half22float2(*(__half2*)&u.x);
        float2 h1v = __half22float2(*(__half2*)&u.y);
        a0 += p * h0.x; a1 += p * h0.y; a2 += p * h1v.x; a3 += p * h1v.y;
    }
    float inv = 1.f / (l + 1e-16f);

    float4 xv  = *(const float4*)&x[(size_t)w * DIM + lane * 4];
    float4 bgv = *(const float4*)&bg[lane * 4];
    float4 v;
    v.x = xv.x + a0 * inv + bgv.x;
    v.y = xv.y + a1 * inv + bgv.y;
    v.z = xv.z + a2 * inv + bgv.z;
    v.w = xv.w + a3 * inv + bgv.w;

    float s = v.x + v.y + v.z + v.w;
    #pragma unroll
    for (int o = 16; o > 0; o >>= 1) s += __shfl_xor_sync(0xFFFFFFFFu, s, o);
    float mu = s * (1.f / DIM);
    v.x -= mu; v.y -= mu; v.z -= mu; v.w -= mu;
    float q = v.x * v.x + v.y * v.y + v.z * v.z + v.w * v.w;
    #pragma unroll
    for (int o = 16; o > 0; o >>= 1) q += __shfl_xor_sync(0xFFFFFFFFu, q, o);
    float rs = rsqrtf(q * (1.f / DIM) + LNEPS);
    float4 g  = *(const float4*)&gamma[lane * 4];
    float4 be = *(const float4*)&beta[lane * 4];
    float4 o4;
    o4.x = g.x * v.x * rs + be.x;
    o4.y = g.y * v.y * rs + be.y;
    o4.z = g.z * v.z * rs + be.z;
    o4.w = g.w * v.w * rs + be.w;
    *(float4*)&h1[(size_t)w * DIM + lane * 4] = o4;
}

// ---------------- launcher: forked capture branches ---------------------------
extern "C" void kernel_launch(void* const* d_in, const int* in_sizes, int n_in,
                              void* d_out, int out_size)
{
    const float* x     = (const float*)d_in[0];
    const void*  ei    = d_in[1];
    const float* Wg    = (const float*)d_in[2];
    const float* att_s = (const float*)d_in[3];
    const float* att_d = (const float*)d_in[4];
    const float* bg    = (const float*)d_in[5];
    const float* gamma = (const float*)d_in[6];
    const float* beta  = (const float*)d_in[7];
    const float* W1    = (const float*)d_in[8];
    const float* b1    = (const float*)d_in[9];
    const float* W2    = (const float*)d_in[10];
    const float* b2    = (const float*)d_in[11];
    float*       out   = (float*)d_out;

    // side stream + fork/join events (leaked; capture-safe)
    cudaStream_t sB;
    cudaStreamCreateWithFlags(&sB, cudaStreamNonBlocking);
    cudaEvent_t evFork, evJoin;
    cudaEventCreateWithFlags(&evFork, cudaEventDisableTiming);
    cudaEventCreateWithFlags(&evJoin, cudaEventDisableTiming);

    cudaEventRecord(evFork, 0);
    cudaStreamWaitEvent(sB, evFork, 0);

    // Branch A (main stream): edge/CSR pipeline (rank-based, atomic-free scatter)
    k_prep<<<(NN + 255) / 256, 256>>>((const unsigned int*)ei);
    k_hist<<<(NE + 255) / 256, 256>>>(ei);
    k_scan_part<<<SCAN_NB, 1024>>>();
    k_scan_tops<<<1, 128>>>();
    k_scan_add<<<SCAN_NB, 1024>>>();
    k_scatter<<<(NE + 255) / 256, 256>>>(ei);

    // Branch B (side stream): weights + feature GEMM + attn coefficients
    k_convT_all<<<(WTOT + 255) / 256, 256, 0, sB>>>(Wg, W1, W2);
    k_gemm1<<<GB_ROWS, 256, 0, sB>>>(x);
    k_attn<<<(NN * HEADS + 255) / 256, 256, 0, sB>>>(att_s, att_d);

    cudaEventRecord(evJoin, sB);
    cudaStreamWaitEvent(0, evJoin, 0);

    // Joined tail
    k_agg_ln<<<(NN * 32 + 255) / 256, 256>>>(x, bg, gamma, beta, out);
    k_ffn1t<<<dim3(GB_ROWS, HID / 128), 256>>>(out, b1);
    k_ffn2t<<<GB_ROWS, 256>>>(b2, gamma, beta, out);
}

// round 16
// speedup vs baseline: 1.0629x; 1.0071x over previous
#include <cuda_runtime.h>
#include <cuda_fp16.h>
#include <math.h>

#define NN    100000
#define DIM   128
#define HEADS 8
#define NE    1600000
#define NEG   0.2f
#define LNEPS 1e-5f
#define HID   512
#define GB_ROWS 782            // ceil(NN/128)
#define SCAN_NB 98             // ceil(NN/1024)

#define OFF_WG 0
#define OFF_W1 16384           // 128*128
#define OFF_W2 81920           // + 128*512
#define WTOT   147456          // + 512*128

// ---------------- scratch (static device globals; no allocation) -------------
__device__ __half g_h16 [(size_t)NN * DIM];   // x@Wg (fp16)
__device__ __half g_z   [(size_t)NN * HID];   // FFN hidden (fp16)
__device__ float  g_asrc[NN * HEADS];
__device__ float  g_adst[NN * HEADS];
__device__ __half g_wT  [WTOT];               // W^T fp16 [n][k]
__device__ int    g_counts  [NN];
__device__ int    g_rank    [NE];             // edge rank within dst bucket
__device__ int    g_offsets [NN + 1];         // block-local exclusive (+blockoff)
__device__ int    g_csr     [NE];
__device__ int    g_blocksum[SCAN_NB];
__device__ int    g_blockoff[SCAN_NB];
__device__ int    g_is64;

// global offset of node i (offsets[NN] is already global)
__device__ __forceinline__ int node_off(int i) {
    return (i < NN) ? g_offsets[i] + g_blockoff[i >> 10] : g_offsets[NN];
}

// ---------------- prep: zero counters + edge dtype detection ------------------
__global__ void k_prep(const unsigned int* __restrict__ ew) {
    int i = blockIdx.x * blockDim.x + threadIdx.x;
    if (i < NN) g_counts[i] = 0;
    if (i == 0) {
        unsigned int acc = 0;
        #pragma unroll
        for (int t = 0; t < 16; ++t) acc |= ew[2 * t + 1];
        g_is64 = (acc == 0) ? 1 : 0;
    }
}

__device__ __forceinline__ int edge_at(const void* ei, int is64, size_t idx) {
    if (is64) return (int)((const long long*)ei)[idx];
    return ((const int*)ei)[idx];
}

__global__ void k_hist(const void* __restrict__ ei) {
    int i = blockIdx.x * blockDim.x + threadIdx.x;
    if (i >= NE) return;
    int dst = edge_at(ei, g_is64, (size_t)NE + i);
    if ((unsigned)dst < (unsigned)NN)
        g_rank[i] = atomicAdd(&g_counts[dst], 1);
}

__global__ __launch_bounds__(1024) void k_scan_part() {
    __shared__ int ws[32];
    int tid = threadIdx.x;
    int i = blockIdx.x * 1024 + tid;
    int v = (i < NN) ? g_counts[i] : 0;
    int lane = tid & 31, wid = tid >> 5;
    int x = v;
    #pragma unroll
    for (int o = 1; o < 32; o <<= 1) {
        int y = __shfl_up_sync(0xFFFFFFFFu, x, o);
        if (lane >= o) x += y;
    }
    if (lane == 31) ws[wid] = x;
    __syncthreads();
    if (wid == 0) {
        int s = ws[lane];
        #pragma unroll
        for (int o = 1; o < 32; o <<= 1) {
            int y = __shfl_up_sync(0xFFFFFFFFu, s, o);
            if (lane >= o) s += y;
        }
        ws[lane] = s;
    }
    __syncthreads();
    int base = wid ? ws[wid - 1] : 0;
    int incl = base + x;
    if (i < NN) g_offsets[i] = incl - v;     // block-local exclusive
    if (tid == 1023) g_blocksum[blockIdx.x] = incl;
}

__global__ void k_scan_tops() {
    __shared__ int ws[4];
    int t = threadIdx.x;
    int v = (t < SCAN_NB) ? g_blocksum[t] : 0;
    int lane = t & 31, wid = t >> 5;
    int x = v;
    #pragma unroll
    for (int o = 1; o < 32; o <<= 1) {
        int y = __shfl_up_sync(0xFFFFFFFFu, x, o);
        if (lane >= o) x += y;
    }
    if (lane == 31) ws[wid] = x;
    __syncthreads();
    int add = 0;
    for (int w = 0; w < wid; ++w) add += ws[w];
    x += add;
    if (t < SCAN_NB) g_blockoff[t] = x - v;
    if (t == SCAN_NB - 1) g_offsets[NN] = x;  // grand total (global)
}

// scatter: pure load/store (rank precomputed); blockoff folded in
__global__ void k_scatter(const void* __restrict__ ei) {
    int i = blockIdx.x * blockDim.x + threadIdx.x;
    if (i >= NE) return;
    int src = edge_at(ei, g_is64, i);
    int dst = edge_at(ei, g_is64, (size_t)NE + i);
    if ((unsigned)src < (unsigned)NN && (unsigned)dst < (unsigned)NN)
        g_csr[g_offsets[dst] + g_blockoff[dst >> 10] + g_rank[i]] = src;
}

// -------- all-weights convert+transpose (fp32 [k][n] -> fp16 [n][k]) ----------
__global__ void k_convT_all(const float* __restrict__ Wg,
                            const float* __restrict__ W1,
                            const float* __restrict__ W2) {
    int i = blockIdx.x * blockDim.x + threadIdx.x;
    if (i >= WTOT) return;
    const float* src; int K, N, off, loc;
    if (i < OFF_W1)      { src = Wg; K = DIM; N = DIM; off = OFF_WG; loc = i; }
    else if (i < OFF_W2) { src = W1; K = DIM; N = HID; off = OFF_W1; loc = i - OFF_W1; }
    else                 { src = W2; K = HID; N = DIM; off = OFF_W2; loc = i - OFF_W2; }
    int k = loc / N, n = loc % N;
    g_wT[off + n * K + k] = __float2half_rn(src[loc]);
}

// ---------------- pipelined fp16 tensor-core GEMM ----------------------------
__device__ __forceinline__ void mma_f16(float* c, const unsigned* a,
                                        unsigned b0, unsigned b1) {
    asm volatile(
        "mma.sync.aligned.m16n8k16.row.col.f32.f16.f16.f32 "
        "{%0,%1,%2,%3}, {%4,%5,%6,%7}, {%8,%9}, {%0,%1,%2,%3};"
        : "+f"(c[0]), "+f"(c[1]), "+f"(c[2]), "+f"(c[3])
        : "r"(a[0]), "r"(a[1]), "r"(a[2]), "r"(a[3]), "r"(b0), "r"(b1));
}
__device__ __forceinline__ unsigned smem_u32(const void* p) {
    return (unsigned)__cvta_generic_to_shared(p);
}
__device__ __forceinline__ void cp16(unsigned dst, const void* src) {
    asm volatile("cp.async.cg.shared.global [%0], [%1], 16;"
                 :: "r"(dst), "l"(src));
}
__device__ __forceinline__ void cp_commit() {
    asm volatile("cp.async.commit_group;");
}
__device__ __forceinline__ void cp_wait0() {
    asm volatile("cp.async.wait_group 0;");
}
__device__ __forceinline__ float gelu_exact(float t) {
    return 0.5f * t * (1.0f + erff(t * 0.70710678118654752f));
}

// EPI: 0 = plain fp16 store; 1 = bias+gelu fp16 store; 2 = bias+residual+LN2
template<bool A_HALF, int EPI>
__device__ __forceinline__ void gemm_body(
    const void* __restrict__ Ap,
    const __half* __restrict__ BT,
    const float* __restrict__ bias,
    __half* __restrict__ Ch,
    float* __restrict__ io,
    const float* __restrict__ gamma, const float* __restrict__ beta,
    int M, int N, int K, int rowTile, int colTile)
{
    __shared__ __half sA[2][128][40];
    __shared__ __half sB[2][128][40];
    __shared__ float  redS[2][128];
    __shared__ float  redQ[2][128];

    const int tid  = threadIdx.x;
    const int lane = tid & 31;
    const int wid  = tid >> 5;
    const int warpM = wid & 3;
    const int warpN = wid >> 2;
    const int rowBase = rowTile * 128;
    const int colBase = colTile * 128;
    const int nc = K >> 5;                   // KC = 32

    auto load_chunk = [&](int c, int st) {
        int k0 = c * 32;
        if (A_HALF) {
            const __half* A = (const __half*)Ap;
            #pragma unroll
            for (int t = 0; t < 2; ++t) {
                int s = tid + t * 256;
                int m = s >> 2, ko = (s & 3) * 8;
                int gr = rowBase + m;
                const void* gp = &A[(size_t)(gr < M ? gr : 0) * K + k0 + ko];
                cp16(smem_u32(&sA[st][m][ko]), gp);
            }
        } else {
            const float* A = (const float*)Ap;
            #pragma unroll
            for (int t = 0; t < 4; ++t) {
                int s = tid + t * 256;
                int m = s >> 3, kq = s & 7;
                int gr = rowBase + m;
                float4 v = (gr < M) ? *(const float4*)&A[(size_t)gr * K + k0 + kq * 4]
                                    : make_float4(0.f, 0.f, 0.f, 0.f);
                *(__half2*)&sA[st][m][kq * 4]     = __floats2half2_rn(v.x, v.y);
                *(__half2*)&sA[st][m][kq * 4 + 2] = __floats2half2_rn(v.z, v.w);
            }
        }
        #pragma unroll
        for (int t = 0; t < 2; ++t) {
            int s = tid + t * 256;
            int n = s >> 2, ko = (s & 3) * 8;
            cp16(smem_u32(&sB[st][n][ko]),
                 &BT[(size_t)(colBase + n) * K + k0 + ko]);
        }
        cp_commit();
    };

    float acc[2][8][4];
    #pragma unroll
    for (int mi = 0; mi < 2; ++mi)
        #pragma unroll
        for (int ni = 0; ni < 8; ++ni)
            #pragma unroll
            for (int q = 0; q < 4; ++q) acc[mi][ni][q] = 0.f;

    load_chunk(0, 0);
    for (int c = 0; c < nc; ++c) {
        cp_wait0();
        __syncthreads();
        if (c + 1 < nc) load_chunk(c + 1, (c + 1) & 1);
        const int st = c & 1;

        #pragma unroll
        for (int ks = 0; ks < 2; ++ks) {
            unsigned ah[2][4];
            #pragma unroll
            for (int mi = 0; mi < 2; ++mi) {
                int r0 = warpM * 32 + mi * 16 + (lane >> 2);
                int r1 = r0 + 8;
                int c0 = ks * 16 + (lane & 3) * 2;
                int c1 = c0 + 8;
                ah[mi][0] = *(const unsigned*)&sA[st][r0][c0];
                ah[mi][1] = *(const unsigned*)&sA[st][r1][c0];
                ah[mi][2] = *(const unsigned*)&sA[st][r0][c1];
                ah[mi][3] = *(const unsigned*)&sA[st][r1][c1];
            }
            #pragma unroll
            for (int ni = 0; ni < 8; ++ni) {
                int nr = warpN * 64 + ni * 8 + (lane >> 2);
                int c0 = ks * 16 + (lane & 3) * 2;
                unsigned b0 = *(const unsigned*)&sB[st][nr][c0];
                unsigned b1 = *(const unsigned*)&sB[st][nr][c0 + 8];
                mma_f16(acc[0][ni], ah[0], b0, b1);
                mma_f16(acc[1][ni], ah[1], b0, b1);
            }
        }
        __syncthreads();
    }

    if (EPI == 0 || EPI == 1) {
        #pragma unroll
        for (int mi = 0; mi < 2; ++mi) {
            int r0 = rowBase + warpM * 32 + mi * 16 + (lane >> 2);
            int r1 = r0 + 8;
            #pragma unroll
            for (int ni = 0; ni < 8; ++ni) {
                int c = colBase + warpN * 64 + ni * 8 + (lane & 3) * 2;
                float b0 = 0.f, b1v = 0.f;
                if (EPI == 1) { b0 = bias[c]; b1v = bias[c + 1]; }
                float x0 = acc[mi][ni][0] + b0, x1 = acc[mi][ni][1] + b1v;
                float x2 = acc[mi][ni][2] + b0, x3 = acc[mi][ni][3] + b1v;
                if (EPI == 1) {
                    x0 = gelu_exact(x0); x1 = gelu_exact(x1);
                    x2 = gelu_exact(x2); x3 = gelu_exact(x3);
                }
                if (r0 < M) *(__half2*)&Ch[(size_t)r0 * N + c] = __floats2half2_rn(x0, x1);
                if (r1 < M) *(__half2*)&Ch[(size_t)r1 * N + c] = __floats2half2_rn(x2, x3);
            }
        }
    } else {
        float sS[2][2] = {{0.f, 0.f}, {0.f, 0.f}};
        float sQ[2][2] = {{0.f, 0.f}, {0.f, 0.f}};
        #pragma unroll
        for (int mi = 0; mi < 2; ++mi) {
            int r0 = rowBase + warpM * 32 + mi * 16 + (lane >> 2);
            int r1 = r0 + 8;
            #pragma unroll
            for (int ni = 0; ni < 8; ++ni) {
                int c = warpN * 64 + ni * 8 + (lane & 3) * 2;
                float bb0 = bias[c], bb1 = bias[c + 1];
                float2 i0 = (r0 < M) ? *(const float2*)&io[(size_t)r0 * N + c]
                                     : make_float2(0.f, 0.f);
                float2 i1 = (r1 < M) ? *(const float2*)&io[(size_t)r1 * N + c]
                                     : make_float2(0.f, 0.f);
                float v0 = acc[mi][ni][0] + bb0 + i0.x;
                float v1 = acc[mi][ni][1] + bb1 + i0.y;
                float v2 = acc[mi][ni][2] + bb0 + i1.x;
                float v3 = acc[mi][ni][3] + bb1 + i1.y;
                acc[mi][ni][0] = v0; acc[mi][ni][1] = v1;
                acc[mi][ni][2] = v2; acc[mi][ni][3] = v3;
                sS[mi][0] += v0 + v1;       sS[mi][1] += v2 + v3;
                sQ[mi][0] += v0*v0 + v1*v1; sQ[mi][1] += v2*v2 + v3*v3;
            }
        }
        #pragma unroll
        for (int mi = 0; mi < 2; ++mi)
            #pragma unroll
            for (int k = 0; k < 2; ++k)
                #pragma unroll
                for (int o = 1; o < 4; o <<= 1) {
                    sS[mi][k] += __shfl_xor_sync(0xFFFFFFFFu, sS[mi][k], o);
                    sQ[mi][k] += __shfl_xor_sync(0xFFFFFFFFu, sQ[mi][k], o);
                }
        if ((lane & 3) == 0) {
            #pragma unroll
            for (int mi = 0; mi < 2; ++mi) {
                int lr = warpM * 32 + mi * 16 + (lane >> 2);
                redS[warpN][lr]     = sS[mi][0];
                redS[warpN][lr + 8] = sS[mi][1];
                redQ[warpN][lr]     = sQ[mi][0];
                redQ[warpN][lr + 8] = sQ[mi][1];
            }
        }
        __syncthreads();
        #pragma unroll
        for (int mi = 0; mi < 2; ++mi) {
            int lr0 = warpM * 32 + mi * 16 + (lane >> 2);
            int lr1 = lr0 + 8;
            float S0 = redS[0][lr0] + redS[1][lr0];
            float S1 = redS[0][lr1] + redS[1][lr1];
            float Q0 = redQ[0][lr0] + redQ[1][lr0];
            float Q1 = redQ[0][lr1] + redQ[1][lr1];
            float mu0 = S0 * (1.f / DIM), mu1 = S1 * (1.f / DIM);
            float rs0 = rsqrtf(fmaxf(Q0 * (1.f / DIM) - mu0 * mu0, 0.f) + LNEPS);
            float rs1 = rsqrtf(fmaxf(Q1 * (1.f / DIM) - mu1 * mu1, 0.f) + LNEPS);
            int r0 = rowBase + lr0;
            int r1 = rowBase + lr1;
            #pragma unroll
            for (int ni = 0; ni < 8; ++ni) {
                int c = warpN * 64 + ni * 8 + (lane & 3) * 2;
                float2 gv = *(const float2*)&gamma[c];
                float2 bv = *(const float2*)&beta[c];
                if (r0 < M) {
                    float2 o0;
                    o0.x = gv.x * (acc[mi][ni][0] - mu0) * rs0 + bv.x;
                    o0.y = gv.y * (acc[mi][ni][1] - mu0) * rs0 + bv.y;
                    *(float2*)&io[(size_t)r0 * N + c] = o0;
                }
                if (r1 < M) {
                    float2 o1;
                    o1.x = gv.x * (acc[mi][ni][2] - mu1) * rs1 + bv.x;
                    o1.y = gv.y * (acc[mi][ni][3] - mu1) * rs1 + bv.y;
                    *(float2*)&io[(size_t)r1 * N + c] = o1;
                }
            }
        }
    }
}

__global__ __launch_bounds__(256) void k_gemm1(const float* __restrict__ x) {
    gemm_body<false, 0>(x, g_wT + OFF_WG, nullptr, g_h16, nullptr,
                        nullptr, nullptr, NN, DIM, DIM, blockIdx.x, 0);
}
__global__ __launch_bounds__(256) void k_ffn1t(const float* __restrict__ h1,
                                               const float* __restrict__ b1) {
    gemm_body<false, 1>(h1, g_wT + OFF_W1, b1, g_z, nullptr,
                        nullptr, nullptr, NN, HID, DIM, blockIdx.x, blockIdx.y);
}
__global__ __launch_bounds__(256) void k_ffn2t(const float* __restrict__ b2,
                                               const float* __restrict__ gamma,
                                               const float* __restrict__ beta,
                                               float* __restrict__ io) {
    gemm_body<true, 2>(g_z, g_wT + OFF_W2, b2, nullptr, io,
                       gamma, beta, NN, DIM, HID, blockIdx.x, 0);
}

// ---------------- attention coefficients (fp16 h) -----------------------------
__global__ void k_attn(const float* __restrict__ att_s,
                       const float* __restrict__ att_d) {
    int idx = blockIdx.x * blockDim.x + threadIdx.x;
    if (idx >= NN * HEADS) return;
    int n = idx >> 3, hh = idx & 7;
    const __half* hr = &g_h16[(size_t)n * DIM + hh * 16];
    float s1 = 0.f, s2 = 0.f;
    #pragma unroll
    for (int k = 0; k < 8; ++k) {
        float2 hv = __half22float2(*(const __half2*)&hr[k * 2]);
        s1 = fmaf(hv.x, att_s[hh * 16 + k * 2],     s1);
        s1 = fmaf(hv.y, att_s[hh * 16 + k * 2 + 1], s1);
        s2 = fmaf(hv.x, att_d[hh * 16 + k * 2],     s2);
        s2 = fmaf(hv.y, att_d[hh * 16 + k * 2 + 1], s2);
    }
    g_asrc[idx] = s1;
    g_adst[idx] = s2;
}

// -------- single-pass aggregation + residual + LN1 (1 warp / node) -----------
__device__ __forceinline__ float leaky(float v) { return fmaxf(v, NEG * v); }

__global__ __launch_bounds__(256) void k_agg_ln(
    const float* __restrict__ x, const float* __restrict__ bg,
    const float* __restrict__ gamma, const float* __restrict__ beta,
    float* __restrict__ h1)
{
    int w = (blockIdx.x * blockDim.x + threadIdx.x) >> 5;
    if (w >= NN) return;
    const int lane = threadIdx.x & 31;
    const int myh = lane >> 2;

    const float adm  = g_adst[w * 8 + myh];
    const float asm_ = g_asrc[w * 8 + myh];

    const int beg = node_off(w);
    const int end = node_off(w + 1);

    float l = 0.f;
    float a0 = 0.f, a1 = 0.f, a2 = 0.f, a3 = 0.f;
    {   // self loop
        float p = __expf(leaky(asm_ + adm));
        l += p;
        uint2 u = *(const uint2*)&g_h16[(size_t)w * DIM + lane * 4];
        float2 h0 = __half22float2(*(__half2*)&u.x);
        float2 h1v = __half22float2(*(__half2*)&u.y);
        a0 += p * h0.x; a1 += p * h0.y; a2 += p * h1v.x; a3 += p * h1v.y;
    }
    int j = beg;
    // unroll 8: all loads hoisted -> 8 independent gather chains
    for (; j + 7 < end; j += 8) {
        int si[8];
        #pragma unroll
        for (int t = 0; t < 8; ++t) si[t] = g_csr[j + t];
        float av[8];
        #pragma unroll
        for (int t = 0; t < 8; ++t) av[t] = g_asrc[si[t] * 8 + myh];
        uint2 uv[8];
        #pragma unroll
        for (int t = 0; t < 8; ++t)
            uv[t] = *(const uint2*)&g_h16[(size_t)si[t] * DIM + lane * 4];
        #pragma unroll
        for (int t = 0; t < 8; ++t) {
            float p = __expf(leaky(av[t] + adm));
            l += p;
            float2 h0 = __half22float2(*(__half2*)&uv[t].x);
            float2 h1v = __half22float2(*(__half2*)&uv[t].y);
            a0 += p * h0.x; a1 += p * h0.y; a2 += p * h1v.x; a3 += p * h1v.y;
        }
    }
    for (; j + 3 < end; j += 4) {
        int s0 = g_csr[j],     s1 = g_csr[j + 1];
        int s2 = g_csr[j + 2], s3 = g_csr[j + 3];
        float p0 = __expf(leaky(g_asrc[s0 * 8 + myh] + adm));
        float p1 = __expf(leaky(g_asrc[s1 * 8 + myh] + adm));
        float p2 = __expf(leaky(g_asrc[s2 * 8 + myh] + adm));
        float p3 = __expf(leaky(g_asrc[s3 * 8 + myh] + adm));
        uint2 u0 = *(const uint2*)&g_h16[(size_t)s0 * DIM + lane * 4];
        uint2 u1 = *(const uint2*)&g_h16[(size_t)s1 * DIM + lane * 4];
        uint2 u2 = *(const uint2*)&g_h16[(size_t)s2 * DIM + lane * 4];
        uint2 u3 = *(const uint2*)&g_h16[(size_t)s3 * DIM + lane * 4];
        l += p0 + p1 + p2 + p3;
        float2 q0 = __half22float2(*(__half2*)&u0.x);
        float2 q1 = __half22float2(*(__half2*)&u0.y);
        float2 r0 = __half22float2(*(__half2*)&u1.x);
        float2 r1 = __half22float2(*(__half2*)&u1.y);
        float2 t0 = __half22float2(*(__half2*)&u2.x);
        float2 t1 = __half22float2(*(__half2*)&u2.y);
        float2 v0 = __half22float2(*(__half2*)&u3.x);
        float2 v1 = __half22float2(*(__half2*)&u3.y);
        a0 += p0 * q0.x + p1 * r0.x + p2 * t0.x + p3 * v0.x;
        a1 += p0 * q0.y + p1 * r0.y + p2 * t0.y + p3 * v0.y;
        a2 += p0 * q1.x + p1 * r1.x + p2 * t1.x + p3 * v1.x;
        a3 += p0 * q1.y + p1 * r1.y + p2 * t1.y + p3 * v1.y;
    }
    for (; j < end; ++j) {
        int s = g_csr[j];
        float p = __expf(leaky(g_asrc[s * 8 + myh] + adm));
        l += p;
        uint2 u = *(const uint2*)&g_h16[(size_t)s * DIM + lane * 4];
        float2 h0 = __half22float2(*(__half2*)&u.x);
        float2 h1v = __half22float2(*(__half2*)&u.y);
        a0 += p * h0.x; a1 += p * h0.y; a2 += p * h1v.x; a3 += p * h1v.y;
    }
    float inv = 1.f / (l + 1e-16f);

    float4 xv  = *(const float4*)&x[(size_t)w * DIM + lane * 4];
    float4 bgv = *(const float4*)&bg[lane * 4];
    float4 v;
    v.x = xv.x + a0 * inv + bgv.x;
    v.y = xv.y + a1 * inv + bgv.y;
    v.z = xv.z + a2 * inv + bgv.z;
    v.w = xv.w + a3 * inv + bgv.w;

    float s = v.x + v.y + v.z + v.w;
    #pragma unroll
    for (int o = 16; o > 0; o >>= 1) s += __shfl_xor_sync(0xFFFFFFFFu, s, o);
    float mu = s * (1.f / DIM);
    v.x -= mu; v.y -= mu; v.z -= mu; v.w -= mu;
    float q = v.x * v.x + v.y * v.y + v.z * v.z + v.w * v.w;
    #pragma unroll
    for (int o = 16; o > 0; o >>= 1) q += __shfl_xor_sync(0xFFFFFFFFu, q, o);
    float rs = rsqrtf(q * (1.f / DIM) + LNEPS);
    float4 g  = *(const float4*)&gamma[lane * 4];
    float4 be = *(const float4*)&beta[lane * 4];
    float4 o4;
    o4.x = g.x * v.x * rs + be.x;
    o4.y = g.y * v.y * rs + be.y;
    o4.z = g.z * v.z * rs + be.z;
    o4.w = g.w * v.w * rs + be.w;
    *(float4*)&h1[(size_t)w * DIM + lane * 4] = o4;
}

// ---------------- launcher: forked capture branches ---------------------------
extern "C" void kernel_launch(void* const* d_in, const int* in_sizes, int n_in,
                              void* d_out, int out_size)
{
    const float* x     = (const float*)d_in[0];
    const void*  ei    = d_in[1];
    const float* Wg    = (const float*)d_in[2];
    const float* att_s = (const float*)d_in[3];
    const float* att_d = (const float*)d_in[4];
    const float* bg    = (const float*)d_in[5];
    const float* gamma = (const float*)d_in[6];
    const float* beta  = (const float*)d_in[7];
    const float* W1    = (const float*)d_in[8];
    const float* b1    = (const float*)d_in[9];
    const float* W2    = (const float*)d_in[10];
    const float* b2    = (const float*)d_in[11];
    float*       out   = (float*)d_out;

    // side stream + fork/join events (leaked; capture-safe)
    cudaStream_t sB;
    cudaStreamCreateWithFlags(&sB, cudaStreamNonBlocking);
    cudaEvent_t evFork, evJoin;
    cudaEventCreateWithFlags(&evFork, cudaEventDisableTiming);
    cudaEventCreateWithFlags(&evJoin, cudaEventDisableTiming);

    cudaEventRecord(evFork, 0);
    cudaStreamWaitEvent(sB, evFork, 0);

    // Branch A (main stream): edge/CSR pipeline (no scan_add kernel)
    k_prep<<<(NN + 255) / 256, 256>>>((const unsigned int*)ei);
    k_hist<<<(NE + 255) / 256, 256>>>(ei);
    k_scan_part<<<SCAN_NB, 1024>>>();
    k_scan_tops<<<1, 128>>>();
    k_scatter<<<(NE + 255) / 256, 256>>>(ei);

    // Branch B (side stream): weights + feature GEMM + attn coefficients
    k_convT_all<<<(WTOT + 255) / 256, 256, 0, sB>>>(Wg, W1, W2);
    k_gemm1<<<GB_ROWS, 256, 0, sB>>>(x);
    k_attn<<<(NN * HEADS + 255) / 256, 256, 0, sB>>>(att_s, att_d);

    cudaEventRecord(evJoin, sB);
    cudaStreamWaitEvent(0, evJoin, 0);

    // Joined tail
    k_agg_ln<<<(NN * 32 + 255) / 256, 256>>>(x, bg, gamma, beta, out);
    k_ffn1t<<<dim3(GB_ROWS, HID / 128), 256>>>(out, b1);
    k_ffn2t<<<GB_ROWS, 256>>>(b2, gamma, beta, out);
}